// round 13
// baseline (speedup 1.0000x reference)
#include <cuda_runtime.h>
#include <cuda_fp16.h>
#include <cstdint>
#include <cstddef>

// Problem constants
#define PB   4
#define PLQ  1024
#define PLK  2048
#define PE   512
#define PHID 512
#define PH   8
#define PHD  64

// ---------------------------------------------------------------------------
// Scratch (__device__ globals; no runtime allocation allowed)
// ---------------------------------------------------------------------------
__device__ float  g_QM[PB * PLQ * PE];
__device__ float  g_Pp[PB * PLQ * PE];
__device__ float  g_X1[PB * PLQ * PE];
__device__ float  g_Fb[PB * PLQ * PHID];
__device__ float  g_X2[PB * PLQ * PHID];

__device__ __half g_w16 [9 * PE * PE];     // cWq*, cWk, cWv, cWo, sWq*, sWk, sWv, sWo, Wf  (* = prescaled 1/8)
__device__ __half g_keys16[PB * PLK * PE];
__device__ __half g_QM16 [PB * PLQ * PE];
__device__ __half g_Qp16 [PB * PLQ * PE];          // cross Q proj (ld 512)
__device__ __half g_KV16 [PB * PLK * 1024];        // cross K|V proj (ld 1024)
__device__ __half g_QKV16[PB * PLQ * 1536];        // self Q|K|V proj (ld 1536)
__device__ __half g_Op16 [PB * PLQ * PE];
__device__ __half g_X116 [PB * PLQ * PE];
__device__ __half g_X216 [PB * PLQ * PE];

__device__ float  g_bQ  [PE];
__device__ float  g_bKV [1024];
__device__ float  g_bQKV[1536];

__device__ float  g_sm[PB * PH * PLQ];
__device__ float  g_sl[PB * PH * PLQ];

// ---------------------------------------------------------------------------
// helpers
// ---------------------------------------------------------------------------
__device__ __forceinline__ void cpasync16(uint32_t dst, const void* src) {
    asm volatile("cp.async.cg.shared.global [%0], [%1], 16;" :: "r"(dst), "l"(src));
}
__device__ __forceinline__ void cpcommit() {
    asm volatile("cp.async.commit_group;");
}
__device__ __forceinline__ uint32_t packh2(float a, float b) {
    __half2 h = __floats2half2_rn(a, b);
    return *reinterpret_cast<uint32_t*>(&h);
}
#define L2E 1.44269504f

// ---------------------------------------------------------------------------
// GEMM body: C = A @ B^T + bias. CTA tile 128x128x64; 8 warps 2(M)x4(N).
// smem: sA 3*16KB @0, sB 3*16KB @49152 (dynamic >= 98304).
// ---------------------------------------------------------------------------
struct GemmP {
    const __half* A; int lda;
    const __half* B; int ldb;
    float* C32; __half* C16; int ldc;
    const float* bias;
    int K;
    const int* qlen;
};

__device__ void gemm_body(const GemmP p, int bx, int by)
{
    extern __shared__ char smem[];
    const uint32_t baseA = (uint32_t)__cvta_generic_to_shared(smem);
    const uint32_t baseB = baseA + 49152u;

    const int tid  = threadIdx.x;
    const int lane = tid & 31;
    const int warp = tid >> 5;
    const int wm   = warp >> 2;
    const int wn   = warp & 3;
    const int m0   = by * 128;
    const int n0   = bx * 128;

    if (p.qlen) {
        int b = m0 >> 10;
        int local = m0 & 1023;
        if (local >= p.qlen[b]) {
            for (int i = tid; i < 128 * 32; i += 256) {
                int r = i >> 5, c = (i & 31) * 4;
                if (p.C32) *reinterpret_cast<float4*>(p.C32 + (size_t)(m0 + r) * p.ldc + n0 + c) =
                    make_float4(0.f, 0.f, 0.f, 0.f);
                if (p.C16) *reinterpret_cast<uint2*>(p.C16 + (size_t)(m0 + r) * p.ldc + n0 + c) =
                    make_uint2(0u, 0u);
            }
            return;
        }
    }

    auto load_tile = [&](int stage, int k0) {
        #pragma unroll
        for (int i = 0; i < 4; i++) {
            int f = tid + i * 256;
            int r = f >> 3, c = f & 7;
            cpasync16(baseA + (uint32_t)stage * 16384u + (uint32_t)r * 128u + (uint32_t)((c ^ (r & 7)) << 4),
                      p.A + (size_t)(m0 + r) * p.lda + k0 + c * 8);
        }
        #pragma unroll
        for (int i = 0; i < 4; i++) {
            int f = tid + i * 256;
            int r = f >> 3, c = f & 7;
            cpasync16(baseB + (uint32_t)stage * 16384u + (uint32_t)r * 128u + (uint32_t)((c ^ (r & 7)) << 4),
                      p.B + (size_t)(n0 + r) * p.ldb + k0 + c * 8);
        }
        cpcommit();
    };

    float d[4][4][4];
    #pragma unroll
    for (int mi = 0; mi < 4; mi++)
        #pragma unroll
        for (int ni = 0; ni < 4; ni++)
            #pragma unroll
            for (int j = 0; j < 4; j++) d[mi][ni][j] = 0.f;

    const int nt = p.K >> 6;
    load_tile(0, 0);
    if (nt > 1) load_tile(1, 64);

    for (int t = 0; t < nt; t++) {
        if (t < nt - 1) { asm volatile("cp.async.wait_group 1;"); }
        else            { asm volatile("cp.async.wait_group 0;"); }
        __syncthreads();
        if (t + 2 < nt) load_tile((t + 2) % 3, (t + 2) << 6);

        const uint32_t stA = baseA + (uint32_t)(t % 3) * 16384u;
        const uint32_t stB = baseB + (uint32_t)(t % 3) * 16384u;

        #pragma unroll
        for (int ks = 0; ks < 4; ks++) {
            const int kb = ks * 16;
            uint32_t a[4][4], b[4][2];
            #pragma unroll
            for (int mi = 0; mi < 4; mi++) {
                int r  = wm * 64 + mi * 16 + (lane & 15);
                int ck = kb + ((lane >> 4) << 3);
                uint32_t addr = stA + (uint32_t)r * 128u + (uint32_t)((((ck >> 3) ^ (r & 7))) << 4);
                asm volatile("ldmatrix.sync.aligned.m8n8.x4.shared.b16 {%0,%1,%2,%3}, [%4];"
                             : "=r"(a[mi][0]), "=r"(a[mi][1]), "=r"(a[mi][2]), "=r"(a[mi][3])
                             : "r"(addr));
            }
            #pragma unroll
            for (int ni = 0; ni < 4; ni++) {
                int r  = wn * 32 + ni * 8 + (lane & 7);
                int ck = kb + (((lane >> 3) & 1) << 3);
                uint32_t addr = stB + (uint32_t)r * 128u + (uint32_t)((((ck >> 3) ^ (r & 7))) << 4);
                asm volatile("ldmatrix.sync.aligned.m8n8.x2.shared.b16 {%0,%1}, [%2];"
                             : "=r"(b[ni][0]), "=r"(b[ni][1])
                             : "r"(addr));
            }
            #pragma unroll
            for (int mi = 0; mi < 4; mi++)
                #pragma unroll
                for (int ni = 0; ni < 4; ni++) {
                    asm volatile(
                        "mma.sync.aligned.m16n8k16.row.col.f32.f16.f16.f32 "
                        "{%0,%1,%2,%3}, {%4,%5,%6,%7}, {%8,%9}, {%0,%1,%2,%3};"
                        : "+f"(d[mi][ni][0]), "+f"(d[mi][ni][1]),
                          "+f"(d[mi][ni][2]), "+f"(d[mi][ni][3])
                        : "r"(a[mi][0]), "r"(a[mi][1]), "r"(a[mi][2]), "r"(a[mi][3]),
                          "r"(b[ni][0]), "r"(b[ni][1]));
                }
        }
        __syncthreads();
    }

    const int g = lane >> 2, tq = lane & 3;
    #pragma unroll
    for (int mi = 0; mi < 4; mi++) {
        #pragma unroll
        for (int ni = 0; ni < 4; ni++) {
            int rr = m0 + wm * 64 + mi * 16 + g;
            int cc = n0 + wn * 32 + ni * 8 + tq * 2;
            float b0 = 0.f, b1 = 0.f;
            if (p.bias) { b0 = p.bias[cc]; b1 = p.bias[cc + 1]; }
            float o00 = d[mi][ni][0] + b0, o01 = d[mi][ni][1] + b1;
            float o10 = d[mi][ni][2] + b0, o11 = d[mi][ni][3] + b1;
            if (p.C32) {
                *reinterpret_cast<float2*>(p.C32 + (size_t)rr * p.ldc + cc)       = make_float2(o00, o01);
                *reinterpret_cast<float2*>(p.C32 + (size_t)(rr + 8) * p.ldc + cc) = make_float2(o10, o11);
            }
            if (p.C16) {
                *reinterpret_cast<__half2*>(p.C16 + (size_t)rr * p.ldc + cc)       = __floats2half2_rn(o00, o01);
                *reinterpret_cast<__half2*>(p.C16 + (size_t)(rr + 8) * p.ldc + cc) = __floats2half2_rn(o10, o11);
            }
        }
    }
}

// ---------------------------------------------------------------------------
// Weights body: one (qt -> 64-row q-tile, b, kz -> 512-key slice).
// Per 64-key stage loads FULL K rows (all 8 heads, 1KB/row), double-buffered;
// all 8 heads between two barriers. p = exp2(s*log2e + c), c = -m*log2e - log2(l).
// smem: sQ 0..64KB | sK 64KB..192KB (2 stg x 64KB) | sC @196608 (8x64 f32)
// total 198656.
// ---------------------------------------------------------------------------
__device__ void weights_body(int qt, int b, int kz,
                             const __half* __restrict__ Qp, const __half* __restrict__ Kp, int ldk,
                             const float* __restrict__ stats_m, const float* __restrict__ stats_l,
                             const int* __restrict__ q_len, float* __restrict__ wout)
{
    extern __shared__ char smem[];
    float* sC = reinterpret_cast<float*>(smem + 196608);

    const int q0 = qt * 64;
    const int tid = threadIdx.x, lane = tid & 31, warp = tid >> 5;
    const int wm = warp & 3, wn = warp >> 2;
    const int ql = q_len[b];

    if (q0 >= ql) {   // whole tile invalid -> zeros (64 rows x 512 keys)
        #pragma unroll
        for (int i = 0; i < 32; i++) {
            int f = tid + i * 256;
            int r = f >> 7, c = (f & 127) * 4;
            *reinterpret_cast<float4*>(wout + ((size_t)b * PLQ + q0 + r) * PLK + kz * 512 + c) =
                make_float4(0.f, 0.f, 0.f, 0.f);
        }
        return;
    }

    const uint32_t baseQ = (uint32_t)__cvta_generic_to_shared(smem);
    const uint32_t baseK = baseQ + 65536u;

    // stats -> combined constant c = -m*log2e - log2(l)  (8 heads x 64 rows)
    #pragma unroll
    for (int i = 0; i < 2; i++) {
        int j = tid + i * 256;
        int h = j >> 6, r = j & 63;
        size_t idx = ((size_t)b * PH + h) * PLQ + q0 + r;
        sC[j] = -stats_m[idx] * L2E - __log2f(stats_l[idx]);
    }

    // Q tile: 64 rows x 64 chunks(16B), swizzled 1024B rows
    const __half* Qb = Qp + ((size_t)b * PLQ + q0) * PE;
    #pragma unroll
    for (int i = 0; i < 16; i++) {
        int f = tid + i * 256;
        int r = f >> 6, c = f & 63;
        uint32_t off = (uint32_t)r * 1024u + (uint32_t)((((c & 7) ^ (r & 7)) | (c & 56)) << 4);
        cpasync16(baseQ + off, Qb + (size_t)r * PE + c * 8);
    }
    cpcommit();

    // K stage: 64 keys x full 512-half rows (all heads), swizzled 1024B rows
    const __half* Kbase = Kp + ((size_t)b * PLK + kz * 512) * ldk;
    auto loadK = [&](int stage, int kt) {
        #pragma unroll
        for (int i = 0; i < 16; i++) {
            int f = tid + i * 256;
            int r = f >> 6, c = f & 63;
            uint32_t off = (uint32_t)r * 1024u + (uint32_t)((((c & 7) ^ (r & 7)) | (c & 56)) << 4);
            cpasync16(baseK + (uint32_t)stage * 65536u + off, Kbase + (size_t)(kt * 64 + r) * ldk + c * 8);
        }
        cpcommit();
    };
    loadK(0, 0);

    const int g = lane >> 2, tq = lane & 3;
    const int rr  = wm * 16 + g;
    const int rr8 = rr + 8;
    const bool v0 = (q0 + rr)  < ql;
    const bool v1 = (q0 + rr8) < ql;

    for (int it = 0; it < 8; it++) {
        if (it + 1 < 8) {
            loadK((it + 1) & 1, it + 1);
            asm volatile("cp.async.wait_group 1;");
        } else {
            asm volatile("cp.async.wait_group 0;");
        }
        __syncthreads();
        const uint32_t ko = (uint32_t)(it & 1) * 65536u;

        float acc[4][4];
        #pragma unroll
        for (int ni = 0; ni < 4; ni++)
            #pragma unroll
            for (int j = 0; j < 4; j++) acc[ni][j] = 0.f;

        #pragma unroll
        for (int h = 0; h < 8; h++) {
            float d[4][4];
            #pragma unroll
            for (int ni = 0; ni < 4; ni++)
                #pragma unroll
                for (int j = 0; j < 4; j++) d[ni][j] = 0.f;

            #pragma unroll
            for (int ks = 0; ks < 4; ks++) {
                const int kb8 = ks * 2;   // 16-byte chunk offset within head
                uint32_t a[4];
                {
                    int r = wm * 16 + (lane & 15);
                    int c = h * 8 + kb8 + (lane >> 4);
                    uint32_t addr = baseQ + (uint32_t)r * 1024u + (uint32_t)((((c & 7) ^ (r & 7)) | (c & 56)) << 4);
                    asm volatile("ldmatrix.sync.aligned.m8n8.x4.shared.b16 {%0,%1,%2,%3}, [%4];"
                                 : "=r"(a[0]), "=r"(a[1]), "=r"(a[2]), "=r"(a[3]) : "r"(addr));
                }
                #pragma unroll
                for (int ni = 0; ni < 4; ni++) {
                    uint32_t b0, b1;
                    int r = wn * 32 + ni * 8 + (lane & 7);
                    int c = h * 8 + kb8 + ((lane >> 3) & 1);
                    uint32_t addr = baseK + ko + (uint32_t)r * 1024u + (uint32_t)((((c & 7) ^ (r & 7)) | (c & 56)) << 4);
                    asm volatile("ldmatrix.sync.aligned.m8n8.x2.shared.b16 {%0,%1}, [%2];"
                                 : "=r"(b0), "=r"(b1) : "r"(addr));
                    asm volatile(
                        "mma.sync.aligned.m16n8k16.row.col.f32.f16.f16.f32 "
                        "{%0,%1,%2,%3}, {%4,%5,%6,%7}, {%8,%9}, {%0,%1,%2,%3};"
                        : "+f"(d[ni][0]), "+f"(d[ni][1]), "+f"(d[ni][2]), "+f"(d[ni][3])
                        : "r"(a[0]), "r"(a[1]), "r"(a[2]), "r"(a[3]), "r"(b0), "r"(b1));
                }
            }

            float c0 = sC[h * 64 + rr];
            float c1 = sC[h * 64 + rr8];
            #pragma unroll
            for (int ni = 0; ni < 4; ni++) {
                acc[ni][0] += exp2f(fmaf(d[ni][0], L2E, c0));
                acc[ni][1] += exp2f(fmaf(d[ni][1], L2E, c0));
                acc[ni][2] += exp2f(fmaf(d[ni][2], L2E, c1));
                acc[ni][3] += exp2f(fmaf(d[ni][3], L2E, c1));
            }
        }

        int kbase = kz * 512 + it * 64;
        #pragma unroll
        for (int ni = 0; ni < 4; ni++) {
            int cc = kbase + wn * 32 + ni * 8 + tq * 2;
            float2 w0 = v0 ? make_float2(acc[ni][0] * 0.125f, acc[ni][1] * 0.125f)
                           : make_float2(0.f, 0.f);
            float2 w1 = v1 ? make_float2(acc[ni][2] * 0.125f, acc[ni][3] * 0.125f)
                           : make_float2(0.f, 0.f);
            *reinterpret_cast<float2*>(wout + ((size_t)b * PLQ + q0 + rr)  * PLK + cc) = w0;
            *reinterpret_cast<float2*>(wout + ((size_t)b * PLQ + q0 + rr8) * PLK + cc) = w1;
        }
        __syncthreads();
    }
}

// ---------------------------------------------------------------------------
// Kernel wrappers
// ---------------------------------------------------------------------------
__global__ __launch_bounds__(256)
void gemm_kernel(GemmP p) { gemm_body(p, blockIdx.x, blockIdx.y); }

// z=0: GEMM p0 (full grid.xy). z=1: GEMM p1 in the top-left gx1 x gy1 corner.
__global__ __launch_bounds__(256)
void dual_gemm_kernel(GemmP p0, GemmP p1, int gx1, int gy1)
{
    if (blockIdx.z == 0) gemm_body(p0, blockIdx.x, blockIdx.y);
    else if ((int)blockIdx.x < gx1 && (int)blockIdx.y < gy1)
        gemm_body(p1, blockIdx.x, blockIdx.y);
}

// LPT ordering: z < gz-1 -> weights CTAs (long) first; z = gz-1 -> GEMM plane.
// weights index w = wbase + z*(gx*gy) + by*gx + bx; w -> kz(0..3), b, qt(0..15)
__global__ __launch_bounds__(256)
void gemm_weights_kernel(GemmP p,
                         const __half* Qp, const __half* Kp, int ldk,
                         const float* sm, const float* sl,
                         const int* q_len, float* wout, int wbase)
{
    if (blockIdx.z == gridDim.z - 1) { gemm_body(p, blockIdx.x, blockIdx.y); return; }
    int w = wbase + blockIdx.z * (gridDim.x * gridDim.y) + blockIdx.y * gridDim.x + blockIdx.x;
    int kz  = w >> 6;
    int rem = w & 63;
    int b   = rem >> 4;
    int qt  = rem & 15;
    weights_body(qt, b, kz, Qp, Kp, ldk, sm, sl, q_len, wout);
}

// ---------------------------------------------------------------------------
// FA2 flash attention. 256 threads, q-tile 128 rows, KV tile 128 keys (2 halves).
// smem: sQ 0..16KB | sK 16K..48K (2 stg x 16KB) | sV 48K..80K (2 stg)
// ---------------------------------------------------------------------------
__global__ __launch_bounds__(256)
void flash2_kernel(const __half* __restrict__ Q, int ldq,
                   const __half* __restrict__ K, int ldk,
                   const __half* __restrict__ V, int ldv,
                   __half* __restrict__ O,
                   float* __restrict__ stats_m, float* __restrict__ stats_l,
                   int LK, int masked, const int* __restrict__ q_len)
{
    extern __shared__ char smem[];
    const int b = blockIdx.z, h = blockIdx.y, q0 = blockIdx.x * 128;
    const int ql = q_len[b];
    if (q0 >= ql) return;

    const int tid = threadIdx.x, lane = tid & 31, warp = tid >> 5;
    const int limit = masked ? ql : LK;
    const int nt = (limit + 127) >> 7;

    const uint32_t baseQ = (uint32_t)__cvta_generic_to_shared(smem);
    const uint32_t baseK = baseQ + 16384u;
    const uint32_t baseV = baseQ + 49152u;

    const __half* Qb = Q + ((size_t)b * PLQ + q0) * ldq + h * PHD;
    const __half* Kb = K + ((size_t)b * LK) * ldk + h * PHD;
    const __half* Vb = V + ((size_t)b * LK) * ldv + h * PHD;

    #pragma unroll
    for (int i = 0; i < 4; i++) {
        int f = tid + i * 256;
        int r = f >> 3, c = f & 7;
        cpasync16(baseQ + (uint32_t)r * 128u + (uint32_t)((c ^ (r & 7)) << 4),
                  Qb + (size_t)r * ldq + c * 8);
    }
    auto loadKV = [&](int stage, int k0) {
        #pragma unroll
        for (int i = 0; i < 4; i++) {
            int f = tid + i * 256;
            int r = f >> 3, c = f & 7;
            cpasync16(baseK + stage * 16384u + (uint32_t)r * 128u + (uint32_t)((c ^ (r & 7)) << 4),
                      Kb + (size_t)(k0 + r) * ldk + c * 8);
        }
        #pragma unroll
        for (int i = 0; i < 4; i++) {
            int f = tid + i * 256;
            int r = f >> 3, c = f & 7;
            cpasync16(baseV + stage * 16384u + (uint32_t)r * 128u + (uint32_t)((c ^ (r & 7)) << 4),
                      Vb + (size_t)(k0 + r) * ldv + c * 8);
        }
        cpcommit();
    };
    loadKV(0, 0);

    float m0 = -3.0e38f, m1 = -3.0e38f, l0 = 0.f, l1 = 0.f;
    float o[8][4];
    #pragma unroll
    for (int ni = 0; ni < 8; ni++)
        #pragma unroll
        for (int j = 0; j < 4; j++) o[ni][j] = 0.f;

    for (int t = 0; t < nt; t++) {
        if (t + 1 < nt) {
            loadKV((t + 1) & 1, (t + 1) << 7);
            asm volatile("cp.async.wait_group 1;");
        } else {
            asm volatile("cp.async.wait_group 0;");
        }
        __syncthreads();
        const uint32_t kvo = (uint32_t)(t & 1) * 16384u;

        #pragma unroll
        for (int half = 0; half < 2; half++) {
            const int k0 = (t << 7) + (half << 6);
            if (k0 >= limit) break;
            const uint32_t kho = kvo + (uint32_t)half * 8192u;

            float d[8][4];
            #pragma unroll
            for (int ni = 0; ni < 8; ni++)
                #pragma unroll
                for (int j = 0; j < 4; j++) d[ni][j] = 0.f;

            #pragma unroll
            for (int ks = 0; ks < 4; ks++) {
                const int kb = ks * 16;
                uint32_t a[4];
                {
                    int r  = warp * 16 + (lane & 15);
                    int ck = kb + ((lane >> 4) << 3);
                    uint32_t addr = baseQ + (uint32_t)r * 128u + (uint32_t)((((ck >> 3) ^ (r & 7))) << 4);
                    asm volatile("ldmatrix.sync.aligned.m8n8.x4.shared.b16 {%0,%1,%2,%3}, [%4];"
                                 : "=r"(a[0]), "=r"(a[1]), "=r"(a[2]), "=r"(a[3]) : "r"(addr));
                }
                #pragma unroll
                for (int ni = 0; ni < 8; ni++) {
                    uint32_t b0, b1;
                    int r  = ni * 8 + (lane & 7);
                    int ck = kb + (((lane >> 3) & 1) << 3);
                    uint32_t addr = baseK + kho + (uint32_t)r * 128u + (uint32_t)((((ck >> 3) ^ (r & 7))) << 4);
                    asm volatile("ldmatrix.sync.aligned.m8n8.x2.shared.b16 {%0,%1}, [%2];"
                                 : "=r"(b0), "=r"(b1) : "r"(addr));
                    asm volatile(
                        "mma.sync.aligned.m16n8k16.row.col.f32.f16.f16.f32 "
                        "{%0,%1,%2,%3}, {%4,%5,%6,%7}, {%8,%9}, {%0,%1,%2,%3};"
                        : "+f"(d[ni][0]), "+f"(d[ni][1]), "+f"(d[ni][2]), "+f"(d[ni][3])
                        : "r"(a[0]), "r"(a[1]), "r"(a[2]), "r"(a[3]), "r"(b0), "r"(b1));
                }
            }

            const bool doMask = masked && (k0 + 64 > limit);
            float t0 = -3.0e38f, t1 = -3.0e38f;
            #pragma unroll
            for (int ni = 0; ni < 8; ni++) {
                if (doMask) {
                    int c0 = k0 + ni * 8 + (lane & 3) * 2;
                    if (c0 >= limit)     { d[ni][0] = -3.0e38f; d[ni][2] = -3.0e38f; }
                    if (c0 + 1 >= limit) { d[ni][1] = -3.0e38f; d[ni][3] = -3.0e38f; }
                }
                t0 = fmaxf(t0, fmaxf(d[ni][0], d[ni][1]));
                t1 = fmaxf(t1, fmaxf(d[ni][2], d[ni][3]));
            }
            t0 = fmaxf(t0, __shfl_xor_sync(0xffffffffu, t0, 1));
            t0 = fmaxf(t0, __shfl_xor_sync(0xffffffffu, t0, 2));
            t1 = fmaxf(t1, __shfl_xor_sync(0xffffffffu, t1, 1));
            t1 = fmaxf(t1, __shfl_xor_sync(0xffffffffu, t1, 2));
            float mn0 = fmaxf(m0, t0), mn1 = fmaxf(m1, t1);
            float fr0 = __expf(m0 - mn0), fr1 = __expf(m1 - mn1);
            m0 = mn0; m1 = mn1;

            float s0 = 0.f, s1 = 0.f;
            uint32_t pf[8][2];
            #pragma unroll
            for (int ni = 0; ni < 8; ni++) {
                float e0 = __expf(d[ni][0] - mn0), e1 = __expf(d[ni][1] - mn0);
                float e2 = __expf(d[ni][2] - mn1), e3 = __expf(d[ni][3] - mn1);
                s0 += e0 + e1; s1 += e2 + e3;
                pf[ni][0] = packh2(e0, e1);
                pf[ni][1] = packh2(e2, e3);
            }
            s0 += __shfl_xor_sync(0xffffffffu, s0, 1);
            s0 += __shfl_xor_sync(0xffffffffu, s0, 2);
            s1 += __shfl_xor_sync(0xffffffffu, s1, 1);
            s1 += __shfl_xor_sync(0xffffffffu, s1, 2);
            l0 = l0 * fr0 + s0;
            l1 = l1 * fr1 + s1;
            #pragma unroll
            for (int ni = 0; ni < 8; ni++) {
                o[ni][0] *= fr0; o[ni][1] *= fr0;
                o[ni][2] *= fr1; o[ni][3] *= fr1;
            }

            #pragma unroll
            for (int j = 0; j < 4; j++) {
                uint32_t a0 = pf[2 * j][0], a1 = pf[2 * j][1];
                uint32_t a2 = pf[2 * j + 1][0], a3 = pf[2 * j + 1][1];
                #pragma unroll
                for (int ni = 0; ni < 8; ni++) {
                    uint32_t b0, b1;
                    int r = j * 16 + (lane & 15);
                    uint32_t addr = baseV + kho + (uint32_t)r * 128u + (uint32_t)(((ni ^ (r & 7))) << 4);
                    asm volatile("ldmatrix.sync.aligned.m8n8.x2.trans.shared.b16 {%0,%1}, [%2];"
                                 : "=r"(b0), "=r"(b1) : "r"(addr));
                    asm volatile(
                        "mma.sync.aligned.m16n8k16.row.col.f32.f16.f16.f32 "
                        "{%0,%1,%2,%3}, {%4,%5,%6,%7}, {%8,%9}, {%0,%1,%2,%3};"
                        : "+f"(o[ni][0]), "+f"(o[ni][1]), "+f"(o[ni][2]), "+f"(o[ni][3])
                        : "r"(a0), "r"(a1), "r"(a2), "r"(a3), "r"(b0), "r"(b1));
                }
            }
        }
        __syncthreads();
    }

    const int g = lane >> 2, tq = lane & 3;
    const int r0 = warp * 16 + g;
    float il0 = 1.0f / l0, il1 = 1.0f / l1;
    __half* Ob = O + ((size_t)b * PLQ + q0) * PE + h * PHD;
    #pragma unroll
    for (int ni = 0; ni < 8; ni++) {
        int cc = ni * 8 + tq * 2;
        *reinterpret_cast<__half2*>(Ob + (size_t)r0 * PE + cc) =
            __floats2half2_rn(o[ni][0] * il0, o[ni][1] * il0);
        *reinterpret_cast<__half2*>(Ob + (size_t)(r0 + 8) * PE + cc) =
            __floats2half2_rn(o[ni][2] * il1, o[ni][3] * il1);
    }
    if (stats_m && tq == 0) {
        size_t idx = ((size_t)b * PH + h) * PLQ + q0 + r0;
        stats_m[idx] = m0;  stats_l[idx] = l0;
        stats_m[idx + 8] = m1;  stats_l[idx + 8] = l1;
    }
}

// ---------------------------------------------------------------------------
// prep kernel: weight convert (+Wq prescale), keys f32->f16, bias pack, query mask
// grid.x = 2304 + 4096 + 2 + 2048 = 8450, 256 threads
// ---------------------------------------------------------------------------
struct Ptr9 { const float* p[9]; };
__global__ __launch_bounds__(256)
void prep_kernel(Ptr9 ps, __half* __restrict__ w16,
                 const float* __restrict__ keys, __half* __restrict__ keys16,
                 const float* cbq, const float* cbk, const float* cbv,
                 const float* sbq, const float* sbk, const float* sbv,
                 float* bQ, float* bKV, float* bQKV,
                 const float* __restrict__ queries, float* __restrict__ QM,
                 __half* __restrict__ QM16, const int* __restrict__ q_len)
{
    int bid = blockIdx.x;
    int tid = threadIdx.x;
    if (bid < 2304) {
        int m = bid >> 8;
        float sc = (m == 0 || m == 4) ? 0.125f : 1.0f;
        int i = ((bid & 255) * 256 + tid) * 4;
        float4 v = *reinterpret_cast<const float4*>(ps.p[m] + i);
        __half2* o = reinterpret_cast<__half2*>(w16 + (size_t)m * PE * PE + i);
        o[0] = __floats2half2_rn(v.x * sc, v.y * sc);
        o[1] = __floats2half2_rn(v.z * sc, v.w * sc);
    } else if (bid < 2304 + 4096) {
        int i = ((bid - 2304) * 256 + tid) * 4;
        float4 v = *reinterpret_cast<const float4*>(keys + i);
        __half2* o = reinterpret_cast<__half2*>(keys16 + i);
        o[0] = __floats2half2_rn(v.x, v.y);
        o[1] = __floats2half2_rn(v.z, v.w);
    } else if (bid < 2304 + 4096 + 2) {
        int i = (bid - 6400) * 256 + tid;     // 0..511
        bQ[i]          = cbq[i] * 0.125f;
        bKV[i]         = cbk[i];
        bKV[512 + i]   = cbv[i];
        bQKV[i]        = sbq[i] * 0.125f;
        bQKV[512 + i]  = sbk[i];
        bQKV[1024 + i] = sbv[i];
    } else {
        int r = (bid - 6402) * 2 + (tid >> 7);
        int c = (tid & 127);
        bool valid = (r % PLQ) < q_len[r / PLQ];
        float4 v = valid ? reinterpret_cast<const float4*>(queries + (size_t)r * PE)[c]
                         : make_float4(0.f, 0.f, 0.f, 0.f);
        reinterpret_cast<float4*>(QM + (size_t)r * PE)[c] = v;
        __half2* dh = reinterpret_cast<__half2*>(QM16 + (size_t)r * PE) + c * 2;
        dh[0] = __floats2half2_rn(v.x, v.y);
        dh[1] = __floats2half2_rn(v.z, v.w);
    }
}

// ---------------------------------------------------------------------------
// out[r,:] = LN( silu(X + Y) )*g + b ; optional fp16 copy; optional zero rows
// ---------------------------------------------------------------------------
__global__ __launch_bounds__(128)
void add_silu_ln_kernel(const float* __restrict__ X, const float* __restrict__ Y,
                        const float* __restrict__ g, const float* __restrict__ bln,
                        float* __restrict__ out, __half* __restrict__ out16,
                        const int* __restrict__ q_len, int zero_invalid)
{
    constexpr int D = 512;
    int r = blockIdx.x;
    int tid = threadIdx.x;
    int c = tid * 4;

    float4 x = *reinterpret_cast<const float4*>(X + (size_t)r * D + c);
    float4 y = *reinterpret_cast<const float4*>(Y + (size_t)r * D + c);
    float v[4] = {x.x + y.x, x.y + y.y, x.z + y.z, x.w + y.w};

    float s[4], sum = 0.f, sumsq = 0.f;
    #pragma unroll
    for (int i = 0; i < 4; i++) {
        s[i] = v[i] / (1.0f + __expf(-v[i]));
        sum += s[i];
        sumsq += s[i] * s[i];
    }

    __shared__ float r1[128], r2[128];
    r1[tid] = sum; r2[tid] = sumsq; __syncthreads();
    for (int st = 64; st > 0; st >>= 1) {
        if (tid < st) { r1[tid] += r1[tid + st]; r2[tid] += r2[tid + st]; }
        __syncthreads();
    }
    float mu  = r1[0] * (1.0f / D);
    float var = r2[0] * (1.0f / D) - mu * mu;
    float rs  = rsqrtf(var + 1e-5f);

    bool zero = zero_invalid && ((r % PLQ) >= q_len[r / PLQ]);

    float4 gg = *reinterpret_cast<const float4*>(g + c);
    float4 bb = *reinterpret_cast<const float4*>(bln + c);
    float4 o;
    o.x = zero ? 0.f : (s[0] - mu) * rs * gg.x + bb.x;
    o.y = zero ? 0.f : (s[1] - mu) * rs * gg.y + bb.y;
    o.z = zero ? 0.f : (s[2] - mu) * rs * gg.z + bb.z;
    o.w = zero ? 0.f : (s[3] - mu) * rs * gg.w + bb.w;
    *reinterpret_cast<float4*>(out + (size_t)r * D + c) = o;
    if (out16) {
        __half2* oh = reinterpret_cast<__half2*>(out16 + (size_t)r * D + c);
        oh[0] = __floats2half2_rn(o.x, o.y);
        oh[1] = __floats2half2_rn(o.z, o.w);
    }
}

// ---------------------------------------------------------------------------
// Host launcher
// ---------------------------------------------------------------------------
extern "C" void kernel_launch(void* const* d_in, const int* in_sizes, int n_in,
                              void* d_out, int out_size)
{
    const float* queries = (const float*)d_in[0];
    const float* keys    = (const float*)d_in[1];
    const int*   q_len   = (const int*)  d_in[2];
    const float* cWq = (const float*)d_in[3];  const float* cbq = (const float*)d_in[4];
    const float* cWk = (const float*)d_in[5];  const float* cbk = (const float*)d_in[6];
    const float* cWv = (const float*)d_in[7];  const float* cbv = (const float*)d_in[8];
    const float* cWo = (const float*)d_in[9];  const float* cbo = (const float*)d_in[10];
    const float* sWq = (const float*)d_in[11]; const float* sbq = (const float*)d_in[12];
    const float* sWk = (const float*)d_in[13]; const float* sbk = (const float*)d_in[14];
    const float* sWv = (const float*)d_in[15]; const float* sbv = (const float*)d_in[16];
    const float* sWo = (const float*)d_in[17]; const float* sbo = (const float*)d_in[18];
    const float* Wf  = (const float*)d_in[19]; const float* bf  = (const float*)d_in[20];
    const float* g_cross = (const float*)d_in[21]; const float* b_cross = (const float*)d_in[22];
    const float* g_ffn   = (const float*)d_in[23]; const float* b_ffn   = (const float*)d_in[24];
    const float* g_self  = (const float*)d_in[25]; const float* b_self  = (const float*)d_in[26];

    float* out_q = (float*)d_out;
    float* out_w = out_q + (size_t)PB * PLQ * PHID;

    float *QM, *Pp, *X1, *Fb, *X2, *sm, *sl, *bQ, *bKV, *bQKV;
    __half *w16, *keys16, *QM16, *Qp16, *KV16, *QKV16, *Op16, *X116, *X216;
    cudaGetSymbolAddress((void**)&QM,   g_QM);
    cudaGetSymbolAddress((void**)&Pp,   g_Pp);
    cudaGetSymbolAddress((void**)&X1,   g_X1);
    cudaGetSymbolAddress((void**)&Fb,   g_Fb);
    cudaGetSymbolAddress((void**)&X2,   g_X2);
    cudaGetSymbolAddress((void**)&sm,   g_sm);
    cudaGetSymbolAddress((void**)&sl,   g_sl);
    cudaGetSymbolAddress((void**)&bQ,   g_bQ);
    cudaGetSymbolAddress((void**)&bKV,  g_bKV);
    cudaGetSymbolAddress((void**)&bQKV, g_bQKV);
    cudaGetSymbolAddress((void**)&w16,  g_w16);
    cudaGetSymbolAddress((void**)&keys16, g_keys16);
    cudaGetSymbolAddress((void**)&QM16, g_QM16);
    cudaGetSymbolAddress((void**)&Qp16, g_Qp16);
    cudaGetSymbolAddress((void**)&KV16, g_KV16);
    cudaGetSymbolAddress((void**)&QKV16, g_QKV16);
    cudaGetSymbolAddress((void**)&Op16, g_Op16);
    cudaGetSymbolAddress((void**)&X116, g_X116);
    cudaGetSymbolAddress((void**)&X216, g_X216);

    cudaFuncSetAttribute(gemm_kernel,          cudaFuncAttributeMaxDynamicSharedMemorySize, 98304);
    cudaFuncSetAttribute(dual_gemm_kernel,     cudaFuncAttributeMaxDynamicSharedMemorySize, 98304);
    cudaFuncSetAttribute(gemm_weights_kernel,  cudaFuncAttributeMaxDynamicSharedMemorySize, 198656);
    cudaFuncSetAttribute(flash2_kernel,        cudaFuncAttributeMaxDynamicSharedMemorySize, 81920);

    const int MQ = PB * PLQ;   // 4096

    // 1) prep: weight/keys convert, bias pack, query masking (one launch)
    Ptr9 ps;
    ps.p[0] = cWq; ps.p[1] = cWk; ps.p[2] = cWv; ps.p[3] = cWo;
    ps.p[4] = sWq; ps.p[5] = sWk; ps.p[6] = sWv; ps.p[7] = sWo; ps.p[8] = Wf;
    prep_kernel<<<8450, 256>>>(ps, w16, keys, keys16,
                               cbq, cbk, cbv, sbq, sbk, sbv, bQ, bKV, bQKV,
                               queries, QM, QM16, q_len);

    // 2) cross projections: merged K|V GEMM (z=0) + Q GEMM (z=1)
    {
        GemmP pKV { keys16, PE, w16 + 1 * PE * PE, PE, nullptr, KV16, 1024, bKV, PE, nullptr };
        GemmP pQ  { QM16,   PE, w16 + 0 * PE * PE, PE, nullptr, Qp16, PE,   bQ,  PE, q_len };
        dual_gemm_kernel<<<dim3(8, 64, 2), 256, 98304>>>(pKV, pQ, 4, 32);
    }

    // 3) fused cross attention -> Op16 (+ stats)
    flash2_kernel<<<dim3(PLQ / 128, PH, PB), 256, 81920>>>(
        Qp16, PE, KV16, 1024, KV16 + 512, 1024, Op16, sm, sl, PLK, 0, q_len);

    // 4) weights slices 0-127 (z=0, long CTAs first) + cross out-projection (z=1)
    {
        GemmP p { Op16, PE, w16 + 3 * PE * PE, PE, Pp, nullptr, PE, cbo, PE, q_len };
        gemm_weights_kernel<<<dim3(4, 32, 2), 256, 198656>>>(
            p, Qp16, KV16, 1024, sm, sl, q_len, out_w, 0);
    }

    // 5) x1 = LN(silu(cross + qm))
    add_silu_ln_kernel<<<MQ, 128>>>(Pp, QM, g_cross, b_cross, X1, X116, q_len, 0);

    // 6) weights slices 128-255 (z=0) + FFN GEMM (z=1)
    {
        GemmP p { X116, PE, w16 + 8 * PE * PE, PE, Fb, nullptr, PHID, bf, PE, q_len };
        gemm_weights_kernel<<<dim3(4, 32, 2), 256, 198656>>>(
            p, Qp16, KV16, 1024, sm, sl, q_len, out_w, 128);
    }

    // 7) x2 = LN(silu(x1 + ffn))
    add_silu_ln_kernel<<<MQ, 128>>>(X1, Fb, g_ffn, b_ffn, X2, X216, q_len, 0);

    // 8) merged self Q|K|V projection (N=1536)
    {
        GemmP p { X216, PHID, w16 + 4 * PE * PE, PHID, nullptr, QKV16, 1536, bQKV, PHID, q_len };
        gemm_kernel<<<dim3(12, 32), 256, 98304>>>(p);
    }

    // 9) fused self attention (masked keys) -> Op16
    flash2_kernel<<<dim3(PLQ / 128, PH, PB), 256, 81920>>>(
        QKV16, 1536, QKV16 + 512, 1536, QKV16 + 1024, 1536, Op16,
        nullptr, nullptr, PLQ, 1, q_len);

    // 10) self out-projection
    {
        GemmP p { Op16, PHID, w16 + 7 * PE * PE, PHID, Pp, nullptr, PHID, sbo, PHID, q_len };
        gemm_kernel<<<dim3(4, 32), 256, 98304>>>(p);
    }

    // 11) final LN, invalid rows zeroed
    add_silu_ln_kernel<<<MQ, 128>>>(X2, Pp, g_self, b_self, out_q, nullptr, q_len, 1);
}

// round 14
// speedup vs baseline: 1.0639x; 1.0639x over previous
#include <cuda_runtime.h>
#include <cuda_fp16.h>
#include <cstdint>
#include <cstddef>

// Problem constants
#define PB   4
#define PLQ  1024
#define PLK  2048
#define PE   512
#define PHID 512
#define PH   8
#define PHD  64

// PDL: wait for predecessor's memory flush before touching global memory.
#define GDC_WAIT() asm volatile("griddepcontrol.wait;" ::: "memory")

// ---------------------------------------------------------------------------
// Scratch (__device__ globals; no runtime allocation allowed)
// ---------------------------------------------------------------------------
__device__ float  g_QM[PB * PLQ * PE];
__device__ float  g_Pp[PB * PLQ * PE];
__device__ float  g_X1[PB * PLQ * PE];
__device__ float  g_Fb[PB * PLQ * PHID];
__device__ float  g_X2[PB * PLQ * PHID];

__device__ __half g_w16 [9 * PE * PE];     // cWq*, cWk, cWv, cWo, sWq*, sWk, sWv, sWo, Wf (* = prescaled 1/8)
__device__ __half g_keys16[PB * PLK * PE];
__device__ __half g_QM16 [PB * PLQ * PE];
__device__ __half g_Qp16 [PB * PLQ * PE];
__device__ __half g_KV16 [PB * PLK * 1024];
__device__ __half g_QKV16[PB * PLQ * 1536];
__device__ __half g_Op16 [PB * PLQ * PE];
__device__ __half g_X116 [PB * PLQ * PE];
__device__ __half g_X216 [PB * PLQ * PE];

__device__ float  g_bQ  [PE];
__device__ float  g_bKV [1024];
__device__ float  g_bQKV[1536];

__device__ float  g_sm[PB * PH * PLQ];
__device__ float  g_sl[PB * PH * PLQ];

// ---------------------------------------------------------------------------
// helpers
// ---------------------------------------------------------------------------
__device__ __forceinline__ void cpasync16(uint32_t dst, const void* src) {
    asm volatile("cp.async.cg.shared.global [%0], [%1], 16;" :: "r"(dst), "l"(src));
}
__device__ __forceinline__ void cpcommit() {
    asm volatile("cp.async.commit_group;");
}
__device__ __forceinline__ uint32_t packh2(float a, float b) {
    __half2 h = __floats2half2_rn(a, b);
    return *reinterpret_cast<uint32_t*>(&h);
}
#define L2E 1.44269504f

// ---------------------------------------------------------------------------
// GEMM body: C = A @ B^T + bias. CTA tile 128x128x64; 8 warps 2(M)x4(N).
// smem: sA 3*16KB @0, sB 3*16KB @49152 (dynamic >= 98304).
// ---------------------------------------------------------------------------
struct GemmP {
    const __half* A; int lda;
    const __half* B; int ldb;
    float* C32; __half* C16; int ldc;
    const float* bias;
    int K;
    const int* qlen;
};

__device__ void gemm_body(const GemmP p, int bx, int by)
{
    extern __shared__ char smem[];
    const uint32_t baseA = (uint32_t)__cvta_generic_to_shared(smem);
    const uint32_t baseB = baseA + 49152u;

    const int tid  = threadIdx.x;
    const int lane = tid & 31;
    const int warp = tid >> 5;
    const int wm   = warp >> 2;
    const int wn   = warp & 3;
    const int m0   = by * 128;
    const int n0   = bx * 128;

    if (p.qlen) {
        int b = m0 >> 10;
        int local = m0 & 1023;
        if (local >= p.qlen[b]) {
            for (int i = tid; i < 128 * 32; i += 256) {
                int r = i >> 5, c = (i & 31) * 4;
                if (p.C32) *reinterpret_cast<float4*>(p.C32 + (size_t)(m0 + r) * p.ldc + n0 + c) =
                    make_float4(0.f, 0.f, 0.f, 0.f);
                if (p.C16) *reinterpret_cast<uint2*>(p.C16 + (size_t)(m0 + r) * p.ldc + n0 + c) =
                    make_uint2(0u, 0u);
            }
            return;
        }
    }

    auto load_tile = [&](int stage, int k0) {
        #pragma unroll
        for (int i = 0; i < 4; i++) {
            int f = tid + i * 256;
            int r = f >> 3, c = f & 7;
            cpasync16(baseA + (uint32_t)stage * 16384u + (uint32_t)r * 128u + (uint32_t)((c ^ (r & 7)) << 4),
                      p.A + (size_t)(m0 + r) * p.lda + k0 + c * 8);
        }
        #pragma unroll
        for (int i = 0; i < 4; i++) {
            int f = tid + i * 256;
            int r = f >> 3, c = f & 7;
            cpasync16(baseB + (uint32_t)stage * 16384u + (uint32_t)r * 128u + (uint32_t)((c ^ (r & 7)) << 4),
                      p.B + (size_t)(n0 + r) * p.ldb + k0 + c * 8);
        }
        cpcommit();
    };

    float d[4][4][4];
    #pragma unroll
    for (int mi = 0; mi < 4; mi++)
        #pragma unroll
        for (int ni = 0; ni < 4; ni++)
            #pragma unroll
            for (int j = 0; j < 4; j++) d[mi][ni][j] = 0.f;

    const int nt = p.K >> 6;
    load_tile(0, 0);
    if (nt > 1) load_tile(1, 64);

    for (int t = 0; t < nt; t++) {
        if (t < nt - 1) { asm volatile("cp.async.wait_group 1;"); }
        else            { asm volatile("cp.async.wait_group 0;"); }
        __syncthreads();
        if (t + 2 < nt) load_tile((t + 2) % 3, (t + 2) << 6);

        const uint32_t stA = baseA + (uint32_t)(t % 3) * 16384u;
        const uint32_t stB = baseB + (uint32_t)(t % 3) * 16384u;

        #pragma unroll
        for (int ks = 0; ks < 4; ks++) {
            const int kb = ks * 16;
            uint32_t a[4][4], b[4][2];
            #pragma unroll
            for (int mi = 0; mi < 4; mi++) {
                int r  = wm * 64 + mi * 16 + (lane & 15);
                int ck = kb + ((lane >> 4) << 3);
                uint32_t addr = stA + (uint32_t)r * 128u + (uint32_t)((((ck >> 3) ^ (r & 7))) << 4);
                asm volatile("ldmatrix.sync.aligned.m8n8.x4.shared.b16 {%0,%1,%2,%3}, [%4];"
                             : "=r"(a[mi][0]), "=r"(a[mi][1]), "=r"(a[mi][2]), "=r"(a[mi][3])
                             : "r"(addr));
            }
            #pragma unroll
            for (int ni = 0; ni < 4; ni++) {
                int r  = wn * 32 + ni * 8 + (lane & 7);
                int ck = kb + (((lane >> 3) & 1) << 3);
                uint32_t addr = stB + (uint32_t)r * 128u + (uint32_t)((((ck >> 3) ^ (r & 7))) << 4);
                asm volatile("ldmatrix.sync.aligned.m8n8.x2.shared.b16 {%0,%1}, [%2];"
                             : "=r"(b[ni][0]), "=r"(b[ni][1])
                             : "r"(addr));
            }
            #pragma unroll
            for (int mi = 0; mi < 4; mi++)
                #pragma unroll
                for (int ni = 0; ni < 4; ni++) {
                    asm volatile(
                        "mma.sync.aligned.m16n8k16.row.col.f32.f16.f16.f32 "
                        "{%0,%1,%2,%3}, {%4,%5,%6,%7}, {%8,%9}, {%0,%1,%2,%3};"
                        : "+f"(d[mi][ni][0]), "+f"(d[mi][ni][1]),
                          "+f"(d[mi][ni][2]), "+f"(d[mi][ni][3])
                        : "r"(a[mi][0]), "r"(a[mi][1]), "r"(a[mi][2]), "r"(a[mi][3]),
                          "r"(b[ni][0]), "r"(b[ni][1]));
                }
        }
        __syncthreads();
    }

    const int g = lane >> 2, tq = lane & 3;
    #pragma unroll
    for (int mi = 0; mi < 4; mi++) {
        #pragma unroll
        for (int ni = 0; ni < 4; ni++) {
            int rr = m0 + wm * 64 + mi * 16 + g;
            int cc = n0 + wn * 32 + ni * 8 + tq * 2;
            float b0 = 0.f, b1 = 0.f;
            if (p.bias) { b0 = p.bias[cc]; b1 = p.bias[cc + 1]; }
            float o00 = d[mi][ni][0] + b0, o01 = d[mi][ni][1] + b1;
            float o10 = d[mi][ni][2] + b0, o11 = d[mi][ni][3] + b1;
            if (p.C32) {
                *reinterpret_cast<float2*>(p.C32 + (size_t)rr * p.ldc + cc)       = make_float2(o00, o01);
                *reinterpret_cast<float2*>(p.C32 + (size_t)(rr + 8) * p.ldc + cc) = make_float2(o10, o11);
            }
            if (p.C16) {
                *reinterpret_cast<__half2*>(p.C16 + (size_t)rr * p.ldc + cc)       = __floats2half2_rn(o00, o01);
                *reinterpret_cast<__half2*>(p.C16 + (size_t)(rr + 8) * p.ldc + cc) = __floats2half2_rn(o10, o11);
            }
        }
    }
}

// ---------------------------------------------------------------------------
// Weights body: one (qt -> 64-row q-tile, b, kz -> 512-key slice).
// Per 64-key stage loads FULL K rows (all 8 heads, 1KB/row), double-buffered;
// all 8 heads between two barriers. p = exp2(s*log2e + c), c = -m*log2e - log2(l).
// smem: sQ 0..64KB | sK 64KB..192KB (2 stg x 64KB) | sC @196608 (8x64 f32)
// total 198656.
// ---------------------------------------------------------------------------
__device__ void weights_body(int qt, int b, int kz,
                             const __half* __restrict__ Qp, const __half* __restrict__ Kp, int ldk,
                             const float* __restrict__ stats_m, const float* __restrict__ stats_l,
                             const int* __restrict__ q_len, float* __restrict__ wout)
{
    extern __shared__ char smem[];
    float* sC = reinterpret_cast<float*>(smem + 196608);

    const int q0 = qt * 64;
    const int tid = threadIdx.x, lane = tid & 31, warp = tid >> 5;
    const int wm = warp & 3, wn = warp >> 2;
    const int ql = q_len[b];

    if (q0 >= ql) {
        #pragma unroll
        for (int i = 0; i < 32; i++) {
            int f = tid + i * 256;
            int r = f >> 7, c = (f & 127) * 4;
            *reinterpret_cast<float4*>(wout + ((size_t)b * PLQ + q0 + r) * PLK + kz * 512 + c) =
                make_float4(0.f, 0.f, 0.f, 0.f);
        }
        return;
    }

    const uint32_t baseQ = (uint32_t)__cvta_generic_to_shared(smem);
    const uint32_t baseK = baseQ + 65536u;

    #pragma unroll
    for (int i = 0; i < 2; i++) {
        int j = tid + i * 256;
        int h = j >> 6, r = j & 63;
        size_t idx = ((size_t)b * PH + h) * PLQ + q0 + r;
        sC[j] = -stats_m[idx] * L2E - __log2f(stats_l[idx]);
    }

    const __half* Qb = Qp + ((size_t)b * PLQ + q0) * PE;
    #pragma unroll
    for (int i = 0; i < 16; i++) {
        int f = tid + i * 256;
        int r = f >> 6, c = f & 63;
        uint32_t off = (uint32_t)r * 1024u + (uint32_t)((((c & 7) ^ (r & 7)) | (c & 56)) << 4);
        cpasync16(baseQ + off, Qb + (size_t)r * PE + c * 8);
    }
    cpcommit();

    const __half* Kbase = Kp + ((size_t)b * PLK + kz * 512) * ldk;
    auto loadK = [&](int stage, int kt) {
        #pragma unroll
        for (int i = 0; i < 16; i++) {
            int f = tid + i * 256;
            int r = f >> 6, c = f & 63;
            uint32_t off = (uint32_t)r * 1024u + (uint32_t)((((c & 7) ^ (r & 7)) | (c & 56)) << 4);
            cpasync16(baseK + (uint32_t)stage * 65536u + off, Kbase + (size_t)(kt * 64 + r) * ldk + c * 8);
        }
        cpcommit();
    };
    loadK(0, 0);

    const int g = lane >> 2, tq = lane & 3;
    const int rr  = wm * 16 + g;
    const int rr8 = rr + 8;
    const bool v0 = (q0 + rr)  < ql;
    const bool v1 = (q0 + rr8) < ql;

    for (int it = 0; it < 8; it++) {
        if (it + 1 < 8) {
            loadK((it + 1) & 1, it + 1);
            asm volatile("cp.async.wait_group 1;");
        } else {
            asm volatile("cp.async.wait_group 0;");
        }
        __syncthreads();
        const uint32_t ko = (uint32_t)(it & 1) * 65536u;

        float acc[4][4];
        #pragma unroll
        for (int ni = 0; ni < 4; ni++)
            #pragma unroll
            for (int j = 0; j < 4; j++) acc[ni][j] = 0.f;

        for (int h = 0; h < 8; h++) {
            float d[4][4];
            #pragma unroll
            for (int ni = 0; ni < 4; ni++)
                #pragma unroll
                for (int j = 0; j < 4; j++) d[ni][j] = 0.f;

            #pragma unroll
            for (int ks = 0; ks < 4; ks++) {
                const int kb8 = ks * 2;
                uint32_t a[4];
                {
                    int r = wm * 16 + (lane & 15);
                    int c = h * 8 + kb8 + (lane >> 4);
                    uint32_t addr = baseQ + (uint32_t)r * 1024u + (uint32_t)((((c & 7) ^ (r & 7)) | (c & 56)) << 4);
                    asm volatile("ldmatrix.sync.aligned.m8n8.x4.shared.b16 {%0,%1,%2,%3}, [%4];"
                                 : "=r"(a[0]), "=r"(a[1]), "=r"(a[2]), "=r"(a[3]) : "r"(addr));
                }
                #pragma unroll
                for (int ni = 0; ni < 4; ni++) {
                    uint32_t b0, b1;
                    int r = wn * 32 + ni * 8 + (lane & 7);
                    int c = h * 8 + kb8 + ((lane >> 3) & 1);
                    uint32_t addr = baseK + ko + (uint32_t)r * 1024u + (uint32_t)((((c & 7) ^ (r & 7)) | (c & 56)) << 4);
                    asm volatile("ldmatrix.sync.aligned.m8n8.x2.shared.b16 {%0,%1}, [%2];"
                                 : "=r"(b0), "=r"(b1) : "r"(addr));
                    asm volatile(
                        "mma.sync.aligned.m16n8k16.row.col.f32.f16.f16.f32 "
                        "{%0,%1,%2,%3}, {%4,%5,%6,%7}, {%8,%9}, {%0,%1,%2,%3};"
                        : "+f"(d[ni][0]), "+f"(d[ni][1]), "+f"(d[ni][2]), "+f"(d[ni][3])
                        : "r"(a[0]), "r"(a[1]), "r"(a[2]), "r"(a[3]), "r"(b0), "r"(b1));
                }
            }

            float c0 = sC[h * 64 + rr];
            float c1 = sC[h * 64 + rr8];
            #pragma unroll
            for (int ni = 0; ni < 4; ni++) {
                acc[ni][0] += exp2f(fmaf(d[ni][0], L2E, c0));
                acc[ni][1] += exp2f(fmaf(d[ni][1], L2E, c0));
                acc[ni][2] += exp2f(fmaf(d[ni][2], L2E, c1));
                acc[ni][3] += exp2f(fmaf(d[ni][3], L2E, c1));
            }
        }

        int kbase = kz * 512 + it * 64;
        #pragma unroll
        for (int ni = 0; ni < 4; ni++) {
            int cc = kbase + wn * 32 + ni * 8 + tq * 2;
            float2 w0 = v0 ? make_float2(acc[ni][0] * 0.125f, acc[ni][1] * 0.125f)
                           : make_float2(0.f, 0.f);
            float2 w1 = v1 ? make_float2(acc[ni][2] * 0.125f, acc[ni][3] * 0.125f)
                           : make_float2(0.f, 0.f);
            *reinterpret_cast<float2*>(wout + ((size_t)b * PLQ + q0 + rr)  * PLK + cc) = w0;
            *reinterpret_cast<float2*>(wout + ((size_t)b * PLQ + q0 + rr8) * PLK + cc) = w1;
        }
        __syncthreads();
    }
}

// ---------------------------------------------------------------------------
// Kernel wrappers
// ---------------------------------------------------------------------------
__global__ __launch_bounds__(256)
void gemm_kernel(GemmP p) { GDC_WAIT(); gemm_body(p, blockIdx.x, blockIdx.y); }

// z=0: GEMM p0 (full grid.xy). z=1: GEMM p1 in the top-left gx1 x gy1 corner.
__global__ __launch_bounds__(256)
void dual_gemm_kernel(GemmP p0, GemmP p1, int gx1, int gy1)
{
    GDC_WAIT();
    if (blockIdx.z == 0) gemm_body(p0, blockIdx.x, blockIdx.y);
    else if ((int)blockIdx.x < gx1 && (int)blockIdx.y < gy1)
        gemm_body(p1, blockIdx.x, blockIdx.y);
}

// LPT ordering: z=0,1 -> long weights CTAs first; z=2 -> GEMM plane last.
// weights l in 0..255 -> kz(0..3), b, qt(0..15)
__global__ __launch_bounds__(256)
void gemm_weights_kernel(GemmP p,
                         const __half* Qp, const __half* Kp, int ldk,
                         const float* sm, const float* sl,
                         const int* q_len, float* wout)
{
    GDC_WAIT();
    if (blockIdx.z == 2) { gemm_body(p, blockIdx.x, blockIdx.y); return; }
    int l = blockIdx.z * (gridDim.x * gridDim.y) + blockIdx.y * gridDim.x + blockIdx.x;
    int kz  = l >> 6;
    int rem = l & 63;
    int b   = rem >> 4;
    int qt  = rem & 15;
    weights_body(qt, b, kz, Qp, Kp, ldk, sm, sl, q_len, wout);
}

// ---------------------------------------------------------------------------
// FA2 flash attention. 256 threads, q-tile 128 rows, KV tile 128 keys (2 halves).
// smem: sQ 0..16KB | sK 16K..48K (2 stg x 16KB) | sV 48K..80K (2 stg)
// ---------------------------------------------------------------------------
__global__ __launch_bounds__(256)
void flash2_kernel(const __half* __restrict__ Q, int ldq,
                   const __half* __restrict__ K, int ldk,
                   const __half* __restrict__ V, int ldv,
                   __half* __restrict__ O,
                   float* __restrict__ stats_m, float* __restrict__ stats_l,
                   int LK, int masked, const int* __restrict__ q_len)
{
    GDC_WAIT();
    extern __shared__ char smem[];
    const int b = blockIdx.z, h = blockIdx.y, q0 = blockIdx.x * 128;
    const int ql = q_len[b];
    if (q0 >= ql) return;

    const int tid = threadIdx.x, lane = tid & 31, warp = tid >> 5;
    const int limit = masked ? ql : LK;
    const int nt = (limit + 127) >> 7;

    const uint32_t baseQ = (uint32_t)__cvta_generic_to_shared(smem);
    const uint32_t baseK = baseQ + 16384u;
    const uint32_t baseV = baseQ + 49152u;

    const __half* Qb = Q + ((size_t)b * PLQ + q0) * ldq + h * PHD;
    const __half* Kb = K + ((size_t)b * LK) * ldk + h * PHD;
    const __half* Vb = V + ((size_t)b * LK) * ldv + h * PHD;

    #pragma unroll
    for (int i = 0; i < 4; i++) {
        int f = tid + i * 256;
        int r = f >> 3, c = f & 7;
        cpasync16(baseQ + (uint32_t)r * 128u + (uint32_t)((c ^ (r & 7)) << 4),
                  Qb + (size_t)r * ldq + c * 8);
    }
    auto loadKV = [&](int stage, int k0) {
        #pragma unroll
        for (int i = 0; i < 4; i++) {
            int f = tid + i * 256;
            int r = f >> 3, c = f & 7;
            cpasync16(baseK + stage * 16384u + (uint32_t)r * 128u + (uint32_t)((c ^ (r & 7)) << 4),
                      Kb + (size_t)(k0 + r) * ldk + c * 8);
        }
        #pragma unroll
        for (int i = 0; i < 4; i++) {
            int f = tid + i * 256;
            int r = f >> 3, c = f & 7;
            cpasync16(baseV + stage * 16384u + (uint32_t)r * 128u + (uint32_t)((c ^ (r & 7)) << 4),
                      Vb + (size_t)(k0 + r) * ldv + c * 8);
        }
        cpcommit();
    };
    loadKV(0, 0);

    float m0 = -3.0e38f, m1 = -3.0e38f, l0 = 0.f, l1 = 0.f;
    float o[8][4];
    #pragma unroll
    for (int ni = 0; ni < 8; ni++)
        #pragma unroll
        for (int j = 0; j < 4; j++) o[ni][j] = 0.f;

    for (int t = 0; t < nt; t++) {
        if (t + 1 < nt) {
            loadKV((t + 1) & 1, (t + 1) << 7);
            asm volatile("cp.async.wait_group 1;");
        } else {
            asm volatile("cp.async.wait_group 0;");
        }
        __syncthreads();
        const uint32_t kvo = (uint32_t)(t & 1) * 16384u;

        #pragma unroll
        for (int half = 0; half < 2; half++) {
            const int k0 = (t << 7) + (half << 6);
            if (k0 >= limit) break;
            const uint32_t kho = kvo + (uint32_t)half * 8192u;

            float d[8][4];
            #pragma unroll
            for (int ni = 0; ni < 8; ni++)
                #pragma unroll
                for (int j = 0; j < 4; j++) d[ni][j] = 0.f;

            #pragma unroll
            for (int ks = 0; ks < 4; ks++) {
                const int kb = ks * 16;
                uint32_t a[4];
                {
                    int r  = warp * 16 + (lane & 15);
                    int ck = kb + ((lane >> 4) << 3);
                    uint32_t addr = baseQ + (uint32_t)r * 128u + (uint32_t)((((ck >> 3) ^ (r & 7))) << 4);
                    asm volatile("ldmatrix.sync.aligned.m8n8.x4.shared.b16 {%0,%1,%2,%3}, [%4];"
                                 : "=r"(a[0]), "=r"(a[1]), "=r"(a[2]), "=r"(a[3]) : "r"(addr));
                }
                #pragma unroll
                for (int ni = 0; ni < 8; ni++) {
                    uint32_t b0, b1;
                    int r  = ni * 8 + (lane & 7);
                    int ck = kb + (((lane >> 3) & 1) << 3);
                    uint32_t addr = baseK + kho + (uint32_t)r * 128u + (uint32_t)((((ck >> 3) ^ (r & 7))) << 4);
                    asm volatile("ldmatrix.sync.aligned.m8n8.x2.shared.b16 {%0,%1}, [%2];"
                                 : "=r"(b0), "=r"(b1) : "r"(addr));
                    asm volatile(
                        "mma.sync.aligned.m16n8k16.row.col.f32.f16.f16.f32 "
                        "{%0,%1,%2,%3}, {%4,%5,%6,%7}, {%8,%9}, {%0,%1,%2,%3};"
                        : "+f"(d[ni][0]), "+f"(d[ni][1]), "+f"(d[ni][2]), "+f"(d[ni][3])
                        : "r"(a[0]), "r"(a[1]), "r"(a[2]), "r"(a[3]), "r"(b0), "r"(b1));
                }
            }

            const bool doMask = masked && (k0 + 64 > limit);
            float t0 = -3.0e38f, t1 = -3.0e38f;
            #pragma unroll
            for (int ni = 0; ni < 8; ni++) {
                if (doMask) {
                    int c0 = k0 + ni * 8 + (lane & 3) * 2;
                    if (c0 >= limit)     { d[ni][0] = -3.0e38f; d[ni][2] = -3.0e38f; }
                    if (c0 + 1 >= limit) { d[ni][1] = -3.0e38f; d[ni][3] = -3.0e38f; }
                }
                t0 = fmaxf(t0, fmaxf(d[ni][0], d[ni][1]));
                t1 = fmaxf(t1, fmaxf(d[ni][2], d[ni][3]));
            }
            t0 = fmaxf(t0, __shfl_xor_sync(0xffffffffu, t0, 1));
            t0 = fmaxf(t0, __shfl_xor_sync(0xffffffffu, t0, 2));
            t1 = fmaxf(t1, __shfl_xor_sync(0xffffffffu, t1, 1));
            t1 = fmaxf(t1, __shfl_xor_sync(0xffffffffu, t1, 2));
            float mn0 = fmaxf(m0, t0), mn1 = fmaxf(m1, t1);
            float fr0 = __expf(m0 - mn0), fr1 = __expf(m1 - mn1);
            m0 = mn0; m1 = mn1;

            float s0 = 0.f, s1 = 0.f;
            uint32_t pf[8][2];
            #pragma unroll
            for (int ni = 0; ni < 8; ni++) {
                float e0 = __expf(d[ni][0] - mn0), e1 = __expf(d[ni][1] - mn0);
                float e2 = __expf(d[ni][2] - mn1), e3 = __expf(d[ni][3] - mn1);
                s0 += e0 + e1; s1 += e2 + e3;
                pf[ni][0] = packh2(e0, e1);
                pf[ni][1] = packh2(e2, e3);
            }
            s0 += __shfl_xor_sync(0xffffffffu, s0, 1);
            s0 += __shfl_xor_sync(0xffffffffu, s0, 2);
            s1 += __shfl_xor_sync(0xffffffffu, s1, 1);
            s1 += __shfl_xor_sync(0xffffffffu, s1, 2);
            l0 = l0 * fr0 + s0;
            l1 = l1 * fr1 + s1;
            #pragma unroll
            for (int ni = 0; ni < 8; ni++) {
                o[ni][0] *= fr0; o[ni][1] *= fr0;
                o[ni][2] *= fr1; o[ni][3] *= fr1;
            }

            #pragma unroll
            for (int j = 0; j < 4; j++) {
                uint32_t a0 = pf[2 * j][0], a1 = pf[2 * j][1];
                uint32_t a2 = pf[2 * j + 1][0], a3 = pf[2 * j + 1][1];
                #pragma unroll
                for (int ni = 0; ni < 8; ni++) {
                    uint32_t b0, b1;
                    int r = j * 16 + (lane & 15);
                    uint32_t addr = baseV + kho + (uint32_t)r * 128u + (uint32_t)(((ni ^ (r & 7))) << 4);
                    asm volatile("ldmatrix.sync.aligned.m8n8.x2.trans.shared.b16 {%0,%1}, [%2];"
                                 : "=r"(b0), "=r"(b1) : "r"(addr));
                    asm volatile(
                        "mma.sync.aligned.m16n8k16.row.col.f32.f16.f16.f32 "
                        "{%0,%1,%2,%3}, {%4,%5,%6,%7}, {%8,%9}, {%0,%1,%2,%3};"
                        : "+f"(o[ni][0]), "+f"(o[ni][1]), "+f"(o[ni][2]), "+f"(o[ni][3])
                        : "r"(a0), "r"(a1), "r"(a2), "r"(a3), "r"(b0), "r"(b1));
                }
            }
        }
        __syncthreads();
    }

    const int g = lane >> 2, tq = lane & 3;
    const int r0 = warp * 16 + g;
    float il0 = 1.0f / l0, il1 = 1.0f / l1;
    __half* Ob = O + ((size_t)b * PLQ + q0) * PE + h * PHD;
    #pragma unroll
    for (int ni = 0; ni < 8; ni++) {
        int cc = ni * 8 + tq * 2;
        *reinterpret_cast<__half2*>(Ob + (size_t)r0 * PE + cc) =
            __floats2half2_rn(o[ni][0] * il0, o[ni][1] * il0);
        *reinterpret_cast<__half2*>(Ob + (size_t)(r0 + 8) * PE + cc) =
            __floats2half2_rn(o[ni][2] * il1, o[ni][3] * il1);
    }
    if (stats_m && tq == 0) {
        size_t idx = ((size_t)b * PH + h) * PLQ + q0 + r0;
        stats_m[idx] = m0;  stats_l[idx] = l0;
        stats_m[idx + 8] = m1;  stats_l[idx + 8] = l1;
    }
}

// ---------------------------------------------------------------------------
// prep kernel: weight convert (+Wq prescale), keys f32->f16, bias pack, query mask
// grid.x = 2304 + 4096 + 2 + 2048 = 8450, 256 threads
// ---------------------------------------------------------------------------
struct Ptr9 { const float* p[9]; };
__global__ __launch_bounds__(256)
void prep_kernel(Ptr9 ps, __half* __restrict__ w16,
                 const float* __restrict__ keys, __half* __restrict__ keys16,
                 const float* cbq, const float* cbk, const float* cbv,
                 const float* sbq, const float* sbk, const float* sbv,
                 float* bQ, float* bKV, float* bQKV,
                 const float* __restrict__ queries, float* __restrict__ QM,
                 __half* __restrict__ QM16, const int* __restrict__ q_len)
{
    GDC_WAIT();
    int bid = blockIdx.x;
    int tid = threadIdx.x;
    if (bid < 2304) {
        int m = bid >> 8;
        float sc = (m == 0 || m == 4) ? 0.125f : 1.0f;
        int i = ((bid & 255) * 256 + tid) * 4;
        float4 v = *reinterpret_cast<const float4*>(ps.p[m] + i);
        __half2* o = reinterpret_cast<__half2*>(w16 + (size_t)m * PE * PE + i);
        o[0] = __floats2half2_rn(v.x * sc, v.y * sc);
        o[1] = __floats2half2_rn(v.z * sc, v.w * sc);
    } else if (bid < 2304 + 4096) {
        int i = ((bid - 2304) * 256 + tid) * 4;
        float4 v = *reinterpret_cast<const float4*>(keys + i);
        __half2* o = reinterpret_cast<__half2*>(keys16 + i);
        o[0] = __floats2half2_rn(v.x, v.y);
        o[1] = __floats2half2_rn(v.z, v.w);
    } else if (bid < 2304 + 4096 + 2) {
        int i = (bid - 6400) * 256 + tid;     // 0..511
        bQ[i]          = cbq[i] * 0.125f;
        bKV[i]         = cbk[i];
        bKV[512 + i]   = cbv[i];
        bQKV[i]        = sbq[i] * 0.125f;
        bQKV[512 + i]  = sbk[i];
        bQKV[1024 + i] = sbv[i];
    } else {
        int r = (bid - 6402) * 2 + (tid >> 7);
        int c = (tid & 127);
        bool valid = (r % PLQ) < q_len[r / PLQ];
        float4 v = valid ? reinterpret_cast<const float4*>(queries + (size_t)r * PE)[c]
                         : make_float4(0.f, 0.f, 0.f, 0.f);
        reinterpret_cast<float4*>(QM + (size_t)r * PE)[c] = v;
        __half2* dh = reinterpret_cast<__half2*>(QM16 + (size_t)r * PE) + c * 2;
        dh[0] = __floats2half2_rn(v.x, v.y);
        dh[1] = __floats2half2_rn(v.z, v.w);
    }
}

// ---------------------------------------------------------------------------
// out[r,:] = LN( silu(X + Y) )*g + b ; optional fp16 copy; optional zero rows
// ---------------------------------------------------------------------------
__global__ __launch_bounds__(128)
void add_silu_ln_kernel(const float* __restrict__ X, const float* __restrict__ Y,
                        const float* __restrict__ g, const float* __restrict__ bln,
                        float* __restrict__ out, __half* __restrict__ out16,
                        const int* __restrict__ q_len, int zero_invalid)
{
    GDC_WAIT();
    constexpr int D = 512;
    int r = blockIdx.x;
    int tid = threadIdx.x;
    int c = tid * 4;

    float4 x = *reinterpret_cast<const float4*>(X + (size_t)r * D + c);
    float4 y = *reinterpret_cast<const float4*>(Y + (size_t)r * D + c);
    float v[4] = {x.x + y.x, x.y + y.y, x.z + y.z, x.w + y.w};

    float s[4], sum = 0.f, sumsq = 0.f;
    #pragma unroll
    for (int i = 0; i < 4; i++) {
        s[i] = v[i] / (1.0f + __expf(-v[i]));
        sum += s[i];
        sumsq += s[i] * s[i];
    }

    __shared__ float r1[128], r2[128];
    r1[tid] = sum; r2[tid] = sumsq; __syncthreads();
    for (int st = 64; st > 0; st >>= 1) {
        if (tid < st) { r1[tid] += r1[tid + st]; r2[tid] += r2[tid + st]; }
        __syncthreads();
    }
    float mu  = r1[0] * (1.0f / D);
    float var = r2[0] * (1.0f / D) - mu * mu;
    float rs  = rsqrtf(var + 1e-5f);

    bool zero = zero_invalid && ((r % PLQ) >= q_len[r / PLQ]);

    float4 gg = *reinterpret_cast<const float4*>(g + c);
    float4 bb = *reinterpret_cast<const float4*>(bln + c);
    float4 o;
    o.x = zero ? 0.f : (s[0] - mu) * rs * gg.x + bb.x;
    o.y = zero ? 0.f : (s[1] - mu) * rs * gg.y + bb.y;
    o.z = zero ? 0.f : (s[2] - mu) * rs * gg.z + bb.z;
    o.w = zero ? 0.f : (s[3] - mu) * rs * gg.w + bb.w;
    *reinterpret_cast<float4*>(out + (size_t)r * D + c) = o;
    if (out16) {
        __half2* oh = reinterpret_cast<__half2*>(out16 + (size_t)r * D + c);
        oh[0] = __floats2half2_rn(o.x, o.y);
        oh[1] = __floats2half2_rn(o.z, o.w);
    }
}

// ---------------------------------------------------------------------------
// Host launcher (all launches PDL-serialized: dependents pre-launch and wait)
// ---------------------------------------------------------------------------
static cudaLaunchConfig_t make_cfg(dim3 grid, dim3 block, size_t smem,
                                   cudaLaunchAttribute* attr)
{
    attr->id = cudaLaunchAttributeProgrammaticStreamSerialization;
    attr->val.programmaticStreamSerializationAllowed = 1;
    cudaLaunchConfig_t cfg{};
    cfg.gridDim = grid;
    cfg.blockDim = block;
    cfg.dynamicSmemBytes = smem;
    cfg.stream = 0;
    cfg.attrs = attr;
    cfg.numAttrs = 1;
    return cfg;
}

extern "C" void kernel_launch(void* const* d_in, const int* in_sizes, int n_in,
                              void* d_out, int out_size)
{
    const float* queries = (const float*)d_in[0];
    const float* keys    = (const float*)d_in[1];
    const int*   q_len   = (const int*)  d_in[2];
    const float* cWq = (const float*)d_in[3];  const float* cbq = (const float*)d_in[4];
    const float* cWk = (const float*)d_in[5];  const float* cbk = (const float*)d_in[6];
    const float* cWv = (const float*)d_in[7];  const float* cbv = (const float*)d_in[8];
    const float* cWo = (const float*)d_in[9];  const float* cbo = (const float*)d_in[10];
    const float* sWq = (const float*)d_in[11]; const float* sbq = (const float*)d_in[12];
    const float* sWk = (const float*)d_in[13]; const float* sbk = (const float*)d_in[14];
    const float* sWv = (const float*)d_in[15]; const float* sbv = (const float*)d_in[16];
    const float* sWo = (const float*)d_in[17]; const float* sbo = (const float*)d_in[18];
    const float* Wf  = (const float*)d_in[19]; const float* bf  = (const float*)d_in[20];
    const float* g_cross = (const float*)d_in[21]; const float* b_cross = (const float*)d_in[22];
    const float* g_ffn   = (const float*)d_in[23]; const float* b_ffn   = (const float*)d_in[24];
    const float* g_self  = (const float*)d_in[25]; const float* b_self  = (const float*)d_in[26];

    float* out_q = (float*)d_out;
    float* out_w = out_q + (size_t)PB * PLQ * PHID;

    float *QM, *Pp, *X1, *Fb, *X2, *sm, *sl, *bQ, *bKV, *bQKV;
    __half *w16, *keys16, *QM16, *Qp16, *KV16, *QKV16, *Op16, *X116, *X216;
    cudaGetSymbolAddress((void**)&QM,   g_QM);
    cudaGetSymbolAddress((void**)&Pp,   g_Pp);
    cudaGetSymbolAddress((void**)&X1,   g_X1);
    cudaGetSymbolAddress((void**)&Fb,   g_Fb);
    cudaGetSymbolAddress((void**)&X2,   g_X2);
    cudaGetSymbolAddress((void**)&sm,   g_sm);
    cudaGetSymbolAddress((void**)&sl,   g_sl);
    cudaGetSymbolAddress((void**)&bQ,   g_bQ);
    cudaGetSymbolAddress((void**)&bKV,  g_bKV);
    cudaGetSymbolAddress((void**)&bQKV, g_bQKV);
    cudaGetSymbolAddress((void**)&w16,  g_w16);
    cudaGetSymbolAddress((void**)&keys16, g_keys16);
    cudaGetSymbolAddress((void**)&QM16, g_QM16);
    cudaGetSymbolAddress((void**)&Qp16, g_Qp16);
    cudaGetSymbolAddress((void**)&KV16, g_KV16);
    cudaGetSymbolAddress((void**)&QKV16, g_QKV16);
    cudaGetSymbolAddress((void**)&Op16, g_Op16);
    cudaGetSymbolAddress((void**)&X116, g_X116);
    cudaGetSymbolAddress((void**)&X216, g_X216);

    cudaFuncSetAttribute(gemm_kernel,          cudaFuncAttributeMaxDynamicSharedMemorySize, 98304);
    cudaFuncSetAttribute(dual_gemm_kernel,     cudaFuncAttributeMaxDynamicSharedMemorySize, 98304);
    cudaFuncSetAttribute(gemm_weights_kernel,  cudaFuncAttributeMaxDynamicSharedMemorySize, 198656);
    cudaFuncSetAttribute(flash2_kernel,        cudaFuncAttributeMaxDynamicSharedMemorySize, 81920);

    const int MQ = PB * PLQ;   // 4096
    cudaLaunchAttribute at;

    // 1) prep: weight/keys convert, bias pack, query masking (one launch)
    Ptr9 ps;
    ps.p[0] = cWq; ps.p[1] = cWk; ps.p[2] = cWv; ps.p[3] = cWo;
    ps.p[4] = sWq; ps.p[5] = sWk; ps.p[6] = sWv; ps.p[7] = sWo; ps.p[8] = Wf;
    {
        cudaLaunchConfig_t cfg = make_cfg(dim3(8450), dim3(256), 0, &at);
        cudaLaunchKernelEx(&cfg, prep_kernel, ps, w16, keys, keys16,
                           cbq, cbk, cbv, sbq, sbk, sbv, bQ, bKV, bQKV,
                           queries, QM, QM16, q_len);
    }

    // 2) cross projections: merged K|V GEMM (z=0) + Q GEMM (z=1)
    {
        GemmP pKV { keys16, PE, w16 + 1 * PE * PE, PE, nullptr, KV16, 1024, bKV, PE, nullptr };
        GemmP pQ  { QM16,   PE, w16 + 0 * PE * PE, PE, nullptr, Qp16, PE,   bQ,  PE, q_len };
        cudaLaunchConfig_t cfg = make_cfg(dim3(8, 64, 2), dim3(256), 98304, &at);
        cudaLaunchKernelEx(&cfg, dual_gemm_kernel, pKV, pQ, 4, 32);
    }

    // 3) fused cross attention -> Op16 (+ stats)
    {
        cudaLaunchConfig_t cfg = make_cfg(dim3(PLQ / 128, PH, PB), dim3(256), 81920, &at);
        cudaLaunchKernelEx(&cfg, flash2_kernel,
                           (const __half*)Qp16, (int)PE, (const __half*)KV16, 1024,
                           (const __half*)(KV16 + 512), 1024, Op16, sm, sl,
                           (int)PLK, 0, q_len);
    }

    // 4) ALL weights slices (z=0,1, long CTAs first) + cross out-projection (z=2)
    {
        GemmP p { Op16, PE, w16 + 3 * PE * PE, PE, Pp, nullptr, PE, cbo, PE, q_len };
        cudaLaunchConfig_t cfg = make_cfg(dim3(4, 32, 3), dim3(256), 198656, &at);
        cudaLaunchKernelEx(&cfg, gemm_weights_kernel, p,
                           (const __half*)Qp16, (const __half*)KV16, 1024,
                           (const float*)sm, (const float*)sl, q_len, out_w);
    }

    // 5) x1 = LN(silu(cross + qm))
    {
        cudaLaunchConfig_t cfg = make_cfg(dim3(MQ), dim3(128), 0, &at);
        cudaLaunchKernelEx(&cfg, add_silu_ln_kernel,
                           (const float*)Pp, (const float*)QM, g_cross, b_cross,
                           X1, X116, q_len, 0);
    }

    // 6) FFN GEMM
    {
        GemmP p { X116, PE, w16 + 8 * PE * PE, PE, Fb, nullptr, PHID, bf, PE, q_len };
        cudaLaunchConfig_t cfg = make_cfg(dim3(4, 32), dim3(256), 98304, &at);
        cudaLaunchKernelEx(&cfg, gemm_kernel, p);
    }

    // 7) x2 = LN(silu(x1 + ffn))
    {
        cudaLaunchConfig_t cfg = make_cfg(dim3(MQ), dim3(128), 0, &at);
        cudaLaunchKernelEx(&cfg, add_silu_ln_kernel,
                           (const float*)X1, (const float*)Fb, g_ffn, b_ffn,
                           X2, X216, q_len, 0);
    }

    // 8) merged self Q|K|V projection (N=1536)
    {
        GemmP p { X216, PHID, w16 + 4 * PE * PE, PHID, nullptr, QKV16, 1536, bQKV, PHID, q_len };
        cudaLaunchConfig_t cfg = make_cfg(dim3(12, 32), dim3(256), 98304, &at);
        cudaLaunchKernelEx(&cfg, gemm_kernel, p);
    }

    // 9) fused self attention (masked keys) -> Op16
    {
        cudaLaunchConfig_t cfg = make_cfg(dim3(PLQ / 128, PH, PB), dim3(256), 81920, &at);
        cudaLaunchKernelEx(&cfg, flash2_kernel,
                           (const __half*)QKV16, 1536, (const __half*)(QKV16 + 512), 1536,
                           (const __half*)(QKV16 + 1024), 1536, Op16,
                           (float*)nullptr, (float*)nullptr, (int)PLQ, 1, q_len);
    }

    // 10) self out-projection
    {
        GemmP p { Op16, PHID, w16 + 7 * PE * PE, PHID, Pp, nullptr, PHID, sbo, PHID, q_len };
        cudaLaunchConfig_t cfg = make_cfg(dim3(4, 32), dim3(256), 98304, &at);
        cudaLaunchKernelEx(&cfg, gemm_kernel, p);
    }

    // 11) final LN, invalid rows zeroed
    {
        cudaLaunchConfig_t cfg = make_cfg(dim3(MQ), dim3(128), 0, &at);
        cudaLaunchKernelEx(&cfg, add_silu_ln_kernel,
                           (const float*)X2, (const float*)Pp, g_self, b_self,
                           out_q, (__half*)nullptr, q_len, 1);
    }
}

// round 15
// speedup vs baseline: 1.0657x; 1.0017x over previous
#include <cuda_runtime.h>
#include <cuda_fp16.h>
#include <cstdint>
#include <cstddef>

// Problem constants
#define PB   4
#define PLQ  1024
#define PLK  2048
#define PE   512
#define PHID 512
#define PH   8
#define PHD  64

// PDL: wait for predecessor's memory flush before touching global memory.
#define GDC_WAIT() asm volatile("griddepcontrol.wait;" ::: "memory")

// ---------------------------------------------------------------------------
// Scratch (__device__ globals; no runtime allocation allowed)
// ---------------------------------------------------------------------------
__device__ float  g_Pp[PB * PLQ * PE];
__device__ float  g_X1[PB * PLQ * PE];
__device__ float  g_Fb[PB * PLQ * PHID];
__device__ float  g_X2[PB * PLQ * PHID];

__device__ __half g_w16 [9 * PE * PE];     // cWq*, cWk, cWv, cWo, sWq*, sWk, sWv, sWo, Wf (* = prescaled 1/8)
__device__ __half g_keys16[PB * PLK * PE];
__device__ __half g_QM16 [PB * PLQ * PE];
__device__ __half g_Qp16 [PB * PLQ * PE];
__device__ __half g_KV16 [PB * PLK * 1024];
__device__ __half g_QKV16[PB * PLQ * 1536];
__device__ __half g_Op16 [PB * PLQ * PE];
__device__ __half g_X116 [PB * PLQ * PE];
__device__ __half g_X216 [PB * PLQ * PE];

__device__ float  g_bQ  [PE];
__device__ float  g_bKV [1024];
__device__ float  g_bQKV[1536];

__device__ float  g_sm[PB * PH * PLQ];
__device__ float  g_sl[PB * PH * PLQ];

// ---------------------------------------------------------------------------
// helpers
// ---------------------------------------------------------------------------
__device__ __forceinline__ void cpasync16(uint32_t dst, const void* src) {
    asm volatile("cp.async.cg.shared.global [%0], [%1], 16;" :: "r"(dst), "l"(src));
}
__device__ __forceinline__ void cpcommit() {
    asm volatile("cp.async.commit_group;");
}
__device__ __forceinline__ uint32_t packh2(float a, float b) {
    __half2 h = __floats2half2_rn(a, b);
    return *reinterpret_cast<uint32_t*>(&h);
}
__device__ __forceinline__ float ex2a(float x) {   // guaranteed single MUFU EX2
    float y;
    asm("ex2.approx.f32 %0, %1;" : "=f"(y) : "f"(x));
    return y;
}
#define L2E 1.44269504f

// ---------------------------------------------------------------------------
// GEMM body: C = A @ B^T + bias. CTA tile 128x128x64; 8 warps 2(M)x4(N).
// smem: sA 3*16KB @0, sB 3*16KB @49152 (dynamic >= 98304).
// ---------------------------------------------------------------------------
struct GemmP {
    const __half* A; int lda;
    const __half* B; int ldb;
    float* C32; __half* C16; int ldc;
    const float* bias;
    int K;
    const int* qlen;
};

__device__ void gemm_body(const GemmP p, int bx, int by)
{
    extern __shared__ char smem[];
    const uint32_t baseA = (uint32_t)__cvta_generic_to_shared(smem);
    const uint32_t baseB = baseA + 49152u;

    const int tid  = threadIdx.x;
    const int lane = tid & 31;
    const int warp = tid >> 5;
    const int wm   = warp >> 2;
    const int wn   = warp & 3;
    const int m0   = by * 128;
    const int n0   = bx * 128;

    if (p.qlen) {
        int b = m0 >> 10;
        int local = m0 & 1023;
        if (local >= p.qlen[b]) {
            for (int i = tid; i < 128 * 32; i += 256) {
                int r = i >> 5, c = (i & 31) * 4;
                if (p.C32) *reinterpret_cast<float4*>(p.C32 + (size_t)(m0 + r) * p.ldc + n0 + c) =
                    make_float4(0.f, 0.f, 0.f, 0.f);
                if (p.C16) *reinterpret_cast<uint2*>(p.C16 + (size_t)(m0 + r) * p.ldc + n0 + c) =
                    make_uint2(0u, 0u);
            }
            return;
        }
    }

    auto load_tile = [&](int stage, int k0) {
        #pragma unroll
        for (int i = 0; i < 4; i++) {
            int f = tid + i * 256;
            int r = f >> 3, c = f & 7;
            cpasync16(baseA + (uint32_t)stage * 16384u + (uint32_t)r * 128u + (uint32_t)((c ^ (r & 7)) << 4),
                      p.A + (size_t)(m0 + r) * p.lda + k0 + c * 8);
        }
        #pragma unroll
        for (int i = 0; i < 4; i++) {
            int f = tid + i * 256;
            int r = f >> 3, c = f & 7;
            cpasync16(baseB + (uint32_t)stage * 16384u + (uint32_t)r * 128u + (uint32_t)((c ^ (r & 7)) << 4),
                      p.B + (size_t)(n0 + r) * p.ldb + k0 + c * 8);
        }
        cpcommit();
    };

    float d[4][4][4];
    #pragma unroll
    for (int mi = 0; mi < 4; mi++)
        #pragma unroll
        for (int ni = 0; ni < 4; ni++)
            #pragma unroll
            for (int j = 0; j < 4; j++) d[mi][ni][j] = 0.f;

    const int nt = p.K >> 6;
    load_tile(0, 0);
    if (nt > 1) load_tile(1, 64);

    for (int t = 0; t < nt; t++) {
        if (t < nt - 1) { asm volatile("cp.async.wait_group 1;"); }
        else            { asm volatile("cp.async.wait_group 0;"); }
        __syncthreads();
        if (t + 2 < nt) load_tile((t + 2) % 3, (t + 2) << 6);

        const uint32_t stA = baseA + (uint32_t)(t % 3) * 16384u;
        const uint32_t stB = baseB + (uint32_t)(t % 3) * 16384u;

        #pragma unroll
        for (int ks = 0; ks < 4; ks++) {
            const int kb = ks * 16;
            uint32_t a[4][4], b[4][2];
            #pragma unroll
            for (int mi = 0; mi < 4; mi++) {
                int r  = wm * 64 + mi * 16 + (lane & 15);
                int ck = kb + ((lane >> 4) << 3);
                uint32_t addr = stA + (uint32_t)r * 128u + (uint32_t)((((ck >> 3) ^ (r & 7))) << 4);
                asm volatile("ldmatrix.sync.aligned.m8n8.x4.shared.b16 {%0,%1,%2,%3}, [%4];"
                             : "=r"(a[mi][0]), "=r"(a[mi][1]), "=r"(a[mi][2]), "=r"(a[mi][3])
                             : "r"(addr));
            }
            #pragma unroll
            for (int ni = 0; ni < 4; ni++) {
                int r  = wn * 32 + ni * 8 + (lane & 7);
                int ck = kb + (((lane >> 3) & 1) << 3);
                uint32_t addr = stB + (uint32_t)r * 128u + (uint32_t)((((ck >> 3) ^ (r & 7))) << 4);
                asm volatile("ldmatrix.sync.aligned.m8n8.x2.shared.b16 {%0,%1}, [%2];"
                             : "=r"(b[ni][0]), "=r"(b[ni][1])
                             : "r"(addr));
            }
            #pragma unroll
            for (int mi = 0; mi < 4; mi++)
                #pragma unroll
                for (int ni = 0; ni < 4; ni++) {
                    asm volatile(
                        "mma.sync.aligned.m16n8k16.row.col.f32.f16.f16.f32 "
                        "{%0,%1,%2,%3}, {%4,%5,%6,%7}, {%8,%9}, {%0,%1,%2,%3};"
                        : "+f"(d[mi][ni][0]), "+f"(d[mi][ni][1]),
                          "+f"(d[mi][ni][2]), "+f"(d[mi][ni][3])
                        : "r"(a[mi][0]), "r"(a[mi][1]), "r"(a[mi][2]), "r"(a[mi][3]),
                          "r"(b[ni][0]), "r"(b[ni][1]));
                }
        }
        __syncthreads();
    }

    const int g = lane >> 2, tq = lane & 3;
    #pragma unroll
    for (int mi = 0; mi < 4; mi++) {
        #pragma unroll
        for (int ni = 0; ni < 4; ni++) {
            int rr = m0 + wm * 64 + mi * 16 + g;
            int cc = n0 + wn * 32 + ni * 8 + tq * 2;
            float b0 = 0.f, b1 = 0.f;
            if (p.bias) { b0 = p.bias[cc]; b1 = p.bias[cc + 1]; }
            float o00 = d[mi][ni][0] + b0, o01 = d[mi][ni][1] + b1;
            float o10 = d[mi][ni][2] + b0, o11 = d[mi][ni][3] + b1;
            if (p.C32) {
                *reinterpret_cast<float2*>(p.C32 + (size_t)rr * p.ldc + cc)       = make_float2(o00, o01);
                *reinterpret_cast<float2*>(p.C32 + (size_t)(rr + 8) * p.ldc + cc) = make_float2(o10, o11);
            }
            if (p.C16) {
                *reinterpret_cast<__half2*>(p.C16 + (size_t)rr * p.ldc + cc)       = __floats2half2_rn(o00, o01);
                *reinterpret_cast<__half2*>(p.C16 + (size_t)(rr + 8) * p.ldc + cc) = __floats2half2_rn(o10, o11);
            }
        }
    }
}

// ---------------------------------------------------------------------------
// Weights body: one (qt -> 64-row q-tile, b, kz -> 512-key slice).
// Per 64-key stage loads FULL K rows (all 8 heads, 1KB/row), double-buffered;
// all 8 heads between two barriers. p = ex2(s*log2e + c), c = -m*log2e - log2(l).
// smem: sQ 0..64KB | sK 64KB..192KB (2 stg x 64KB) | sC @196608 (8x64 f32)
// total 198656.
// ---------------------------------------------------------------------------
__device__ void weights_body(int qt, int b, int kz,
                             const __half* __restrict__ Qp, const __half* __restrict__ Kp, int ldk,
                             const float* __restrict__ stats_m, const float* __restrict__ stats_l,
                             const int* __restrict__ q_len, float* __restrict__ wout)
{
    extern __shared__ char smem[];
    float* sC = reinterpret_cast<float*>(smem + 196608);

    const int q0 = qt * 64;
    const int tid = threadIdx.x, lane = tid & 31, warp = tid >> 5;
    const int wm = warp & 3, wn = warp >> 2;
    const int ql = q_len[b];

    if (q0 >= ql) {
        #pragma unroll
        for (int i = 0; i < 32; i++) {
            int f = tid + i * 256;
            int r = f >> 7, c = (f & 127) * 4;
            *reinterpret_cast<float4*>(wout + ((size_t)b * PLQ + q0 + r) * PLK + kz * 512 + c) =
                make_float4(0.f, 0.f, 0.f, 0.f);
        }
        return;
    }

    const uint32_t baseQ = (uint32_t)__cvta_generic_to_shared(smem);
    const uint32_t baseK = baseQ + 65536u;

    #pragma unroll
    for (int i = 0; i < 2; i++) {
        int j = tid + i * 256;
        int h = j >> 6, r = j & 63;
        size_t idx = ((size_t)b * PH + h) * PLQ + q0 + r;
        sC[j] = -stats_m[idx] * L2E - __log2f(stats_l[idx]);
    }

    const __half* Qb = Qp + ((size_t)b * PLQ + q0) * PE;
    #pragma unroll
    for (int i = 0; i < 16; i++) {
        int f = tid + i * 256;
        int r = f >> 6, c = f & 63;
        uint32_t off = (uint32_t)r * 1024u + (uint32_t)((((c & 7) ^ (r & 7)) | (c & 56)) << 4);
        cpasync16(baseQ + off, Qb + (size_t)r * PE + c * 8);
    }
    cpcommit();

    const __half* Kbase = Kp + ((size_t)b * PLK + kz * 512) * ldk;
    auto loadK = [&](int stage, int kt) {
        #pragma unroll
        for (int i = 0; i < 16; i++) {
            int f = tid + i * 256;
            int r = f >> 6, c = f & 63;
            uint32_t off = (uint32_t)r * 1024u + (uint32_t)((((c & 7) ^ (r & 7)) | (c & 56)) << 4);
            cpasync16(baseK + (uint32_t)stage * 65536u + off, Kbase + (size_t)(kt * 64 + r) * ldk + c * 8);
        }
        cpcommit();
    };
    loadK(0, 0);

    const int g = lane >> 2, tq = lane & 3;
    const int rr  = wm * 16 + g;
    const int rr8 = rr + 8;
    const bool v0 = (q0 + rr)  < ql;
    const bool v1 = (q0 + rr8) < ql;

    for (int it = 0; it < 8; it++) {
        if (it + 1 < 8) {
            loadK((it + 1) & 1, it + 1);
            asm volatile("cp.async.wait_group 1;");
        } else {
            asm volatile("cp.async.wait_group 0;");
        }
        __syncthreads();
        const uint32_t ko = (uint32_t)(it & 1) * 65536u;

        float acc[4][4];
        #pragma unroll
        for (int ni = 0; ni < 4; ni++)
            #pragma unroll
            for (int j = 0; j < 4; j++) acc[ni][j] = 0.f;

        for (int h = 0; h < 8; h++) {
            float d[4][4];
            #pragma unroll
            for (int ni = 0; ni < 4; ni++)
                #pragma unroll
                for (int j = 0; j < 4; j++) d[ni][j] = 0.f;

            #pragma unroll
            for (int ks = 0; ks < 4; ks++) {
                const int kb8 = ks * 2;
                uint32_t a[4];
                {
                    int r = wm * 16 + (lane & 15);
                    int c = h * 8 + kb8 + (lane >> 4);
                    uint32_t addr = baseQ + (uint32_t)r * 1024u + (uint32_t)((((c & 7) ^ (r & 7)) | (c & 56)) << 4);
                    asm volatile("ldmatrix.sync.aligned.m8n8.x4.shared.b16 {%0,%1,%2,%3}, [%4];"
                                 : "=r"(a[0]), "=r"(a[1]), "=r"(a[2]), "=r"(a[3]) : "r"(addr));
                }
                #pragma unroll
                for (int ni = 0; ni < 4; ni++) {
                    uint32_t b0, b1;
                    int r = wn * 32 + ni * 8 + (lane & 7);
                    int c = h * 8 + kb8 + ((lane >> 3) & 1);
                    uint32_t addr = baseK + ko + (uint32_t)r * 1024u + (uint32_t)((((c & 7) ^ (r & 7)) | (c & 56)) << 4);
                    asm volatile("ldmatrix.sync.aligned.m8n8.x2.shared.b16 {%0,%1}, [%2];"
                                 : "=r"(b0), "=r"(b1) : "r"(addr));
                    asm volatile(
                        "mma.sync.aligned.m16n8k16.row.col.f32.f16.f16.f32 "
                        "{%0,%1,%2,%3}, {%4,%5,%6,%7}, {%8,%9}, {%0,%1,%2,%3};"
                        : "+f"(d[ni][0]), "+f"(d[ni][1]), "+f"(d[ni][2]), "+f"(d[ni][3])
                        : "r"(a[0]), "r"(a[1]), "r"(a[2]), "r"(a[3]), "r"(b0), "r"(b1));
                }
            }

            float c0 = sC[h * 64 + rr];
            float c1 = sC[h * 64 + rr8];
            #pragma unroll
            for (int ni = 0; ni < 4; ni++) {
                acc[ni][0] += ex2a(fmaf(d[ni][0], L2E, c0));
                acc[ni][1] += ex2a(fmaf(d[ni][1], L2E, c0));
                acc[ni][2] += ex2a(fmaf(d[ni][2], L2E, c1));
                acc[ni][3] += ex2a(fmaf(d[ni][3], L2E, c1));
            }
        }

        int kbase = kz * 512 + it * 64;
        #pragma unroll
        for (int ni = 0; ni < 4; ni++) {
            int cc = kbase + wn * 32 + ni * 8 + tq * 2;
            float2 w0 = v0 ? make_float2(acc[ni][0] * 0.125f, acc[ni][1] * 0.125f)
                           : make_float2(0.f, 0.f);
            float2 w1 = v1 ? make_float2(acc[ni][2] * 0.125f, acc[ni][3] * 0.125f)
                           : make_float2(0.f, 0.f);
            *reinterpret_cast<float2*>(wout + ((size_t)b * PLQ + q0 + rr)  * PLK + cc) = w0;
            *reinterpret_cast<float2*>(wout + ((size_t)b * PLQ + q0 + rr8) * PLK + cc) = w1;
        }
        __syncthreads();
    }
}

// ---------------------------------------------------------------------------
// Kernel wrappers
// ---------------------------------------------------------------------------
__global__ __launch_bounds__(256)
void gemm_kernel(GemmP p) { GDC_WAIT(); gemm_body(p, blockIdx.x, blockIdx.y); }

// z=0: GEMM p0 (full grid.xy). z=1: GEMM p1 in the top-left gx1 x gy1 corner.
__global__ __launch_bounds__(256)
void dual_gemm_kernel(GemmP p0, GemmP p1, int gx1, int gy1)
{
    GDC_WAIT();
    if (blockIdx.z == 0) gemm_body(p0, blockIdx.x, blockIdx.y);
    else if ((int)blockIdx.x < gx1 && (int)blockIdx.y < gy1)
        gemm_body(p1, blockIdx.x, blockIdx.y);
}

// LPT ordering: z=0,1 -> long weights CTAs first; z=2 -> GEMM plane last.
// weights l in 0..255 -> kz(0..3), b, qt(0..15)
__global__ __launch_bounds__(256)
void gemm_weights_kernel(GemmP p,
                         const __half* Qp, const __half* Kp, int ldk,
                         const float* sm, const float* sl,
                         const int* q_len, float* wout)
{
    GDC_WAIT();
    if (blockIdx.z == 2) { gemm_body(p, blockIdx.x, blockIdx.y); return; }
    int l = blockIdx.z * (gridDim.x * gridDim.y) + blockIdx.y * gridDim.x + blockIdx.x;
    int kz  = l >> 6;
    int rem = l & 63;
    int b   = rem >> 4;
    int qt  = rem & 15;
    weights_body(qt, b, kz, Qp, Kp, ldk, sm, sl, q_len, wout);
}

// ---------------------------------------------------------------------------
// FA2 flash attention. 256 threads, q-tile 128 rows, KV tile 128 keys (2 halves).
// smem: sQ 0..16KB | sK 16K..48K (2 stg x 16KB) | sV 48K..80K (2 stg)
// ---------------------------------------------------------------------------
__global__ __launch_bounds__(256)
void flash2_kernel(const __half* __restrict__ Q, int ldq,
                   const __half* __restrict__ K, int ldk,
                   const __half* __restrict__ V, int ldv,
                   __half* __restrict__ O,
                   float* __restrict__ stats_m, float* __restrict__ stats_l,
                   int LK, int masked, const int* __restrict__ q_len)
{
    GDC_WAIT();
    extern __shared__ char smem[];
    const int b = blockIdx.z, h = blockIdx.y, q0 = blockIdx.x * 128;
    const int ql = q_len[b];
    if (q0 >= ql) return;

    const int tid = threadIdx.x, lane = tid & 31, warp = tid >> 5;
    const int limit = masked ? ql : LK;
    const int nt = (limit + 127) >> 7;

    const uint32_t baseQ = (uint32_t)__cvta_generic_to_shared(smem);
    const uint32_t baseK = baseQ + 16384u;
    const uint32_t baseV = baseQ + 49152u;

    const __half* Qb = Q + ((size_t)b * PLQ + q0) * ldq + h * PHD;
    const __half* Kb = K + ((size_t)b * LK) * ldk + h * PHD;
    const __half* Vb = V + ((size_t)b * LK) * ldv + h * PHD;

    #pragma unroll
    for (int i = 0; i < 4; i++) {
        int f = tid + i * 256;
        int r = f >> 3, c = f & 7;
        cpasync16(baseQ + (uint32_t)r * 128u + (uint32_t)((c ^ (r & 7)) << 4),
                  Qb + (size_t)r * ldq + c * 8);
    }
    auto loadKV = [&](int stage, int k0) {
        #pragma unroll
        for (int i = 0; i < 4; i++) {
            int f = tid + i * 256;
            int r = f >> 3, c = f & 7;
            cpasync16(baseK + stage * 16384u + (uint32_t)r * 128u + (uint32_t)((c ^ (r & 7)) << 4),
                      Kb + (size_t)(k0 + r) * ldk + c * 8);
        }
        #pragma unroll
        for (int i = 0; i < 4; i++) {
            int f = tid + i * 256;
            int r = f >> 3, c = f & 7;
            cpasync16(baseV + stage * 16384u + (uint32_t)r * 128u + (uint32_t)((c ^ (r & 7)) << 4),
                      Vb + (size_t)(k0 + r) * ldv + c * 8);
        }
        cpcommit();
    };
    loadKV(0, 0);

    float m0 = -3.0e38f, m1 = -3.0e38f, l0 = 0.f, l1 = 0.f;
    float o[8][4];
    #pragma unroll
    for (int ni = 0; ni < 8; ni++)
        #pragma unroll
        for (int j = 0; j < 4; j++) o[ni][j] = 0.f;

    for (int t = 0; t < nt; t++) {
        if (t + 1 < nt) {
            loadKV((t + 1) & 1, (t + 1) << 7);
            asm volatile("cp.async.wait_group 1;");
        } else {
            asm volatile("cp.async.wait_group 0;");
        }
        __syncthreads();
        const uint32_t kvo = (uint32_t)(t & 1) * 16384u;

        #pragma unroll
        for (int half = 0; half < 2; half++) {
            const int k0 = (t << 7) + (half << 6);
            if (k0 >= limit) break;
            const uint32_t kho = kvo + (uint32_t)half * 8192u;

            float d[8][4];
            #pragma unroll
            for (int ni = 0; ni < 8; ni++)
                #pragma unroll
                for (int j = 0; j < 4; j++) d[ni][j] = 0.f;

            #pragma unroll
            for (int ks = 0; ks < 4; ks++) {
                const int kb = ks * 16;
                uint32_t a[4];
                {
                    int r  = warp * 16 + (lane & 15);
                    int ck = kb + ((lane >> 4) << 3);
                    uint32_t addr = baseQ + (uint32_t)r * 128u + (uint32_t)((((ck >> 3) ^ (r & 7))) << 4);
                    asm volatile("ldmatrix.sync.aligned.m8n8.x4.shared.b16 {%0,%1,%2,%3}, [%4];"
                                 : "=r"(a[0]), "=r"(a[1]), "=r"(a[2]), "=r"(a[3]) : "r"(addr));
                }
                #pragma unroll
                for (int ni = 0; ni < 8; ni++) {
                    uint32_t b0, b1;
                    int r  = ni * 8 + (lane & 7);
                    int ck = kb + (((lane >> 3) & 1) << 3);
                    uint32_t addr = baseK + kho + (uint32_t)r * 128u + (uint32_t)((((ck >> 3) ^ (r & 7))) << 4);
                    asm volatile("ldmatrix.sync.aligned.m8n8.x2.shared.b16 {%0,%1}, [%2];"
                                 : "=r"(b0), "=r"(b1) : "r"(addr));
                    asm volatile(
                        "mma.sync.aligned.m16n8k16.row.col.f32.f16.f16.f32 "
                        "{%0,%1,%2,%3}, {%4,%5,%6,%7}, {%8,%9}, {%0,%1,%2,%3};"
                        : "+f"(d[ni][0]), "+f"(d[ni][1]), "+f"(d[ni][2]), "+f"(d[ni][3])
                        : "r"(a[0]), "r"(a[1]), "r"(a[2]), "r"(a[3]), "r"(b0), "r"(b1));
                }
            }

            const bool doMask = masked && (k0 + 64 > limit);
            float t0 = -3.0e38f, t1 = -3.0e38f;
            #pragma unroll
            for (int ni = 0; ni < 8; ni++) {
                if (doMask) {
                    int c0 = k0 + ni * 8 + (lane & 3) * 2;
                    if (c0 >= limit)     { d[ni][0] = -3.0e38f; d[ni][2] = -3.0e38f; }
                    if (c0 + 1 >= limit) { d[ni][1] = -3.0e38f; d[ni][3] = -3.0e38f; }
                }
                t0 = fmaxf(t0, fmaxf(d[ni][0], d[ni][1]));
                t1 = fmaxf(t1, fmaxf(d[ni][2], d[ni][3]));
            }
            t0 = fmaxf(t0, __shfl_xor_sync(0xffffffffu, t0, 1));
            t0 = fmaxf(t0, __shfl_xor_sync(0xffffffffu, t0, 2));
            t1 = fmaxf(t1, __shfl_xor_sync(0xffffffffu, t1, 1));
            t1 = fmaxf(t1, __shfl_xor_sync(0xffffffffu, t1, 2));
            float mn0 = fmaxf(m0, t0), mn1 = fmaxf(m1, t1);
            float fr0 = __expf(m0 - mn0), fr1 = __expf(m1 - mn1);
            m0 = mn0; m1 = mn1;

            float s0 = 0.f, s1 = 0.f;
            uint32_t pf[8][2];
            #pragma unroll
            for (int ni = 0; ni < 8; ni++) {
                float e0 = __expf(d[ni][0] - mn0), e1 = __expf(d[ni][1] - mn0);
                float e2 = __expf(d[ni][2] - mn1), e3 = __expf(d[ni][3] - mn1);
                s0 += e0 + e1; s1 += e2 + e3;
                pf[ni][0] = packh2(e0, e1);
                pf[ni][1] = packh2(e2, e3);
            }
            s0 += __shfl_xor_sync(0xffffffffu, s0, 1);
            s0 += __shfl_xor_sync(0xffffffffu, s0, 2);
            s1 += __shfl_xor_sync(0xffffffffu, s1, 1);
            s1 += __shfl_xor_sync(0xffffffffu, s1, 2);
            l0 = l0 * fr0 + s0;
            l1 = l1 * fr1 + s1;
            #pragma unroll
            for (int ni = 0; ni < 8; ni++) {
                o[ni][0] *= fr0; o[ni][1] *= fr0;
                o[ni][2] *= fr1; o[ni][3] *= fr1;
            }

            #pragma unroll
            for (int j = 0; j < 4; j++) {
                uint32_t a0 = pf[2 * j][0], a1 = pf[2 * j][1];
                uint32_t a2 = pf[2 * j + 1][0], a3 = pf[2 * j + 1][1];
                #pragma unroll
                for (int ni = 0; ni < 8; ni++) {
                    uint32_t b0, b1;
                    int r = j * 16 + (lane & 15);
                    uint32_t addr = baseV + kho + (uint32_t)r * 128u + (uint32_t)(((ni ^ (r & 7))) << 4);
                    asm volatile("ldmatrix.sync.aligned.m8n8.x2.trans.shared.b16 {%0,%1}, [%2];"
                                 : "=r"(b0), "=r"(b1) : "r"(addr));
                    asm volatile(
                        "mma.sync.aligned.m16n8k16.row.col.f32.f16.f16.f32 "
                        "{%0,%1,%2,%3}, {%4,%5,%6,%7}, {%8,%9}, {%0,%1,%2,%3};"
                        : "+f"(o[ni][0]), "+f"(o[ni][1]), "+f"(o[ni][2]), "+f"(o[ni][3])
                        : "r"(a0), "r"(a1), "r"(a2), "r"(a3), "r"(b0), "r"(b1));
                }
            }
        }
        __syncthreads();
    }

    const int g = lane >> 2, tq = lane & 3;
    const int r0 = warp * 16 + g;
    float il0 = 1.0f / l0, il1 = 1.0f / l1;
    __half* Ob = O + ((size_t)b * PLQ + q0) * PE + h * PHD;
    #pragma unroll
    for (int ni = 0; ni < 8; ni++) {
        int cc = ni * 8 + tq * 2;
        *reinterpret_cast<__half2*>(Ob + (size_t)r0 * PE + cc) =
            __floats2half2_rn(o[ni][0] * il0, o[ni][1] * il0);
        *reinterpret_cast<__half2*>(Ob + (size_t)(r0 + 8) * PE + cc) =
            __floats2half2_rn(o[ni][2] * il1, o[ni][3] * il1);
    }
    if (stats_m && tq == 0) {
        size_t idx = ((size_t)b * PH + h) * PLQ + q0 + r0;
        stats_m[idx] = m0;  stats_l[idx] = l0;
        stats_m[idx + 8] = m1;  stats_l[idx + 8] = l1;
    }
}

// ---------------------------------------------------------------------------
// prep kernel: weight convert (+Wq prescale), keys f32->f16, bias pack,
// query mask (fp16 only). grid.x = 2304 + 4096 + 2 + 2048 = 8450, 256 threads
// ---------------------------------------------------------------------------
struct Ptr9 { const float* p[9]; };
__global__ __launch_bounds__(256)
void prep_kernel(Ptr9 ps, __half* __restrict__ w16,
                 const float* __restrict__ keys, __half* __restrict__ keys16,
                 const float* cbq, const float* cbk, const float* cbv,
                 const float* sbq, const float* sbk, const float* sbv,
                 float* bQ, float* bKV, float* bQKV,
                 const float* __restrict__ queries,
                 __half* __restrict__ QM16, const int* __restrict__ q_len)
{
    GDC_WAIT();
    int bid = blockIdx.x;
    int tid = threadIdx.x;
    if (bid < 2304) {
        int m = bid >> 8;
        float sc = (m == 0 || m == 4) ? 0.125f : 1.0f;
        int i = ((bid & 255) * 256 + tid) * 4;
        float4 v = *reinterpret_cast<const float4*>(ps.p[m] + i);
        __half2* o = reinterpret_cast<__half2*>(w16 + (size_t)m * PE * PE + i);
        o[0] = __floats2half2_rn(v.x * sc, v.y * sc);
        o[1] = __floats2half2_rn(v.z * sc, v.w * sc);
    } else if (bid < 2304 + 4096) {
        int i = ((bid - 2304) * 256 + tid) * 4;
        float4 v = *reinterpret_cast<const float4*>(keys + i);
        __half2* o = reinterpret_cast<__half2*>(keys16 + i);
        o[0] = __floats2half2_rn(v.x, v.y);
        o[1] = __floats2half2_rn(v.z, v.w);
    } else if (bid < 2304 + 4096 + 2) {
        int i = (bid - 6400) * 256 + tid;     // 0..511
        bQ[i]          = cbq[i] * 0.125f;
        bKV[i]         = cbk[i];
        bKV[512 + i]   = cbv[i];
        bQKV[i]        = sbq[i] * 0.125f;
        bQKV[512 + i]  = sbk[i];
        bQKV[1024 + i] = sbv[i];
    } else {
        int r = (bid - 6402) * 2 + (tid >> 7);
        int c = (tid & 127);
        bool valid = (r % PLQ) < q_len[r / PLQ];
        float4 v = valid ? reinterpret_cast<const float4*>(queries + (size_t)r * PE)[c]
                         : make_float4(0.f, 0.f, 0.f, 0.f);
        __half2* dh = reinterpret_cast<__half2*>(QM16 + (size_t)r * PE) + c * 2;
        dh[0] = __floats2half2_rn(v.x, v.y);
        dh[1] = __floats2half2_rn(v.z, v.w);
    }
}

// ---------------------------------------------------------------------------
// out[r,:] = LN( silu(X + Y) )*g + b ; optional fp16 copy; optional zero rows
// ---------------------------------------------------------------------------
__global__ __launch_bounds__(128)
void add_silu_ln_kernel(const float* __restrict__ X, const float* __restrict__ Y,
                        const float* __restrict__ g, const float* __restrict__ bln,
                        float* __restrict__ out, __half* __restrict__ out16,
                        const int* __restrict__ q_len, int zero_invalid)
{
    GDC_WAIT();
    constexpr int D = 512;
    int r = blockIdx.x;
    int tid = threadIdx.x;
    int c = tid * 4;

    float4 x = *reinterpret_cast<const float4*>(X + (size_t)r * D + c);
    float4 y = *reinterpret_cast<const float4*>(Y + (size_t)r * D + c);
    float v[4] = {x.x + y.x, x.y + y.y, x.z + y.z, x.w + y.w};

    float s[4], sum = 0.f, sumsq = 0.f;
    #pragma unroll
    for (int i = 0; i < 4; i++) {
        s[i] = v[i] / (1.0f + __expf(-v[i]));
        sum += s[i];
        sumsq += s[i] * s[i];
    }

    __shared__ float r1[128], r2[128];
    r1[tid] = sum; r2[tid] = sumsq; __syncthreads();
    for (int st = 64; st > 0; st >>= 1) {
        if (tid < st) { r1[tid] += r1[tid + st]; r2[tid] += r2[tid + st]; }
        __syncthreads();
    }
    float mu  = r1[0] * (1.0f / D);
    float var = r2[0] * (1.0f / D) - mu * mu;
    float rs  = rsqrtf(var + 1e-5f);

    bool zero = zero_invalid && ((r % PLQ) >= q_len[r / PLQ]);

    float4 gg = *reinterpret_cast<const float4*>(g + c);
    float4 bb = *reinterpret_cast<const float4*>(bln + c);
    float4 o;
    o.x = zero ? 0.f : (s[0] - mu) * rs * gg.x + bb.x;
    o.y = zero ? 0.f : (s[1] - mu) * rs * gg.y + bb.y;
    o.z = zero ? 0.f : (s[2] - mu) * rs * gg.z + bb.z;
    o.w = zero ? 0.f : (s[3] - mu) * rs * gg.w + bb.w;
    *reinterpret_cast<float4*>(out + (size_t)r * D + c) = o;
    if (out16) {
        __half2* oh = reinterpret_cast<__half2*>(out16 + (size_t)r * D + c);
        oh[0] = __floats2half2_rn(o.x, o.y);
        oh[1] = __floats2half2_rn(o.z, o.w);
    }
}

// ---------------------------------------------------------------------------
// Host launcher (all launches PDL-serialized: dependents pre-launch and wait)
// ---------------------------------------------------------------------------
static cudaLaunchConfig_t make_cfg(dim3 grid, dim3 block, size_t smem,
                                   cudaLaunchAttribute* attr)
{
    attr->id = cudaLaunchAttributeProgrammaticStreamSerialization;
    attr->val.programmaticStreamSerializationAllowed = 1;
    cudaLaunchConfig_t cfg{};
    cfg.gridDim = grid;
    cfg.blockDim = block;
    cfg.dynamicSmemBytes = smem;
    cfg.stream = 0;
    cfg.attrs = attr;
    cfg.numAttrs = 1;
    return cfg;
}

extern "C" void kernel_launch(void* const* d_in, const int* in_sizes, int n_in,
                              void* d_out, int out_size)
{
    const float* queries = (const float*)d_in[0];
    const float* keys    = (const float*)d_in[1];
    const int*   q_len   = (const int*)  d_in[2];
    const float* cWq = (const float*)d_in[3];  const float* cbq = (const float*)d_in[4];
    const float* cWk = (const float*)d_in[5];  const float* cbk = (const float*)d_in[6];
    const float* cWv = (const float*)d_in[7];  const float* cbv = (const float*)d_in[8];
    const float* cWo = (const float*)d_in[9];  const float* cbo = (const float*)d_in[10];
    const float* sWq = (const float*)d_in[11]; const float* sbq = (const float*)d_in[12];
    const float* sWk = (const float*)d_in[13]; const float* sbk = (const float*)d_in[14];
    const float* sWv = (const float*)d_in[15]; const float* sbv = (const float*)d_in[16];
    const float* sWo = (const float*)d_in[17]; const float* sbo = (const float*)d_in[18];
    const float* Wf  = (const float*)d_in[19]; const float* bf  = (const float*)d_in[20];
    const float* g_cross = (const float*)d_in[21]; const float* b_cross = (const float*)d_in[22];
    const float* g_ffn   = (const float*)d_in[23]; const float* b_ffn   = (const float*)d_in[24];
    const float* g_self  = (const float*)d_in[25]; const float* b_self  = (const float*)d_in[26];

    float* out_q = (float*)d_out;
    float* out_w = out_q + (size_t)PB * PLQ * PHID;

    float *Pp, *X1, *Fb, *X2, *sm, *sl, *bQ, *bKV, *bQKV;
    __half *w16, *keys16, *QM16, *Qp16, *KV16, *QKV16, *Op16, *X116, *X216;
    cudaGetSymbolAddress((void**)&Pp,   g_Pp);
    cudaGetSymbolAddress((void**)&X1,   g_X1);
    cudaGetSymbolAddress((void**)&Fb,   g_Fb);
    cudaGetSymbolAddress((void**)&X2,   g_X2);
    cudaGetSymbolAddress((void**)&sm,   g_sm);
    cudaGetSymbolAddress((void**)&sl,   g_sl);
    cudaGetSymbolAddress((void**)&bQ,   g_bQ);
    cudaGetSymbolAddress((void**)&bKV,  g_bKV);
    cudaGetSymbolAddress((void**)&bQKV, g_bQKV);
    cudaGetSymbolAddress((void**)&w16,  g_w16);
    cudaGetSymbolAddress((void**)&keys16, g_keys16);
    cudaGetSymbolAddress((void**)&QM16, g_QM16);
    cudaGetSymbolAddress((void**)&Qp16, g_Qp16);
    cudaGetSymbolAddress((void**)&KV16, g_KV16);
    cudaGetSymbolAddress((void**)&QKV16, g_QKV16);
    cudaGetSymbolAddress((void**)&Op16, g_Op16);
    cudaGetSymbolAddress((void**)&X116, g_X116);
    cudaGetSymbolAddress((void**)&X216, g_X216);

    cudaFuncSetAttribute(gemm_kernel,          cudaFuncAttributeMaxDynamicSharedMemorySize, 98304);
    cudaFuncSetAttribute(dual_gemm_kernel,     cudaFuncAttributeMaxDynamicSharedMemorySize, 98304);
    cudaFuncSetAttribute(gemm_weights_kernel,  cudaFuncAttributeMaxDynamicSharedMemorySize, 198656);
    cudaFuncSetAttribute(flash2_kernel,        cudaFuncAttributeMaxDynamicSharedMemorySize, 81920);

    const int MQ = PB * PLQ;   // 4096
    cudaLaunchAttribute at;

    // 1) prep: weight/keys convert, bias pack, query masking (fp16 only)
    Ptr9 ps;
    ps.p[0] = cWq; ps.p[1] = cWk; ps.p[2] = cWv; ps.p[3] = cWo;
    ps.p[4] = sWq; ps.p[5] = sWk; ps.p[6] = sWv; ps.p[7] = sWo; ps.p[8] = Wf;
    {
        cudaLaunchConfig_t cfg = make_cfg(dim3(8450), dim3(256), 0, &at);
        cudaLaunchKernelEx(&cfg, prep_kernel, ps, w16, keys, keys16,
                           cbq, cbk, cbv, sbq, sbk, sbv, bQ, bKV, bQKV,
                           queries, QM16, q_len);
    }

    // 2) cross projections: merged K|V GEMM (z=0) + Q GEMM (z=1)
    {
        GemmP pKV { keys16, PE, w16 + 1 * PE * PE, PE, nullptr, KV16, 1024, bKV, PE, nullptr };
        GemmP pQ  { QM16,   PE, w16 + 0 * PE * PE, PE, nullptr, Qp16, PE,   bQ,  PE, q_len };
        cudaLaunchConfig_t cfg = make_cfg(dim3(8, 64, 2), dim3(256), 98304, &at);
        cudaLaunchKernelEx(&cfg, dual_gemm_kernel, pKV, pQ, 4, 32);
    }

    // 3) fused cross attention -> Op16 (+ stats)
    {
        cudaLaunchConfig_t cfg = make_cfg(dim3(PLQ / 128, PH, PB), dim3(256), 81920, &at);
        cudaLaunchKernelEx(&cfg, flash2_kernel,
                           (const __half*)Qp16, (int)PE, (const __half*)KV16, 1024,
                           (const __half*)(KV16 + 512), 1024, Op16, sm, sl,
                           (int)PLK, 0, q_len);
    }

    // 4) ALL weights slices (z=0,1, long CTAs first) + cross out-projection (z=2)
    {
        GemmP p { Op16, PE, w16 + 3 * PE * PE, PE, Pp, nullptr, PE, cbo, PE, q_len };
        cudaLaunchConfig_t cfg = make_cfg(dim3(4, 32, 3), dim3(256), 198656, &at);
        cudaLaunchKernelEx(&cfg, gemm_weights_kernel, p,
                           (const __half*)Qp16, (const __half*)KV16, 1024,
                           (const float*)sm, (const float*)sl, q_len, out_w);
    }

    // 5) x1 = LN(silu(cross + queries))   (invalid rows garbage-but-finite, dead downstream)
    {
        cudaLaunchConfig_t cfg = make_cfg(dim3(MQ), dim3(128), 0, &at);
        cudaLaunchKernelEx(&cfg, add_silu_ln_kernel,
                           (const float*)Pp, queries, g_cross, b_cross,
                           X1, X116, q_len, 0);
    }

    // 6) FFN GEMM
    {
        GemmP p { X116, PE, w16 + 8 * PE * PE, PE, Fb, nullptr, PHID, bf, PE, q_len };
        cudaLaunchConfig_t cfg = make_cfg(dim3(4, 32), dim3(256), 98304, &at);
        cudaLaunchKernelEx(&cfg, gemm_kernel, p);
    }

    // 7) x2 = LN(silu(x1 + ffn))
    {
        cudaLaunchConfig_t cfg = make_cfg(dim3(MQ), dim3(128), 0, &at);
        cudaLaunchKernelEx(&cfg, add_silu_ln_kernel,
                           (const float*)X1, (const float*)Fb, g_ffn, b_ffn,
                           X2, X216, q_len, 0);
    }

    // 8) merged self Q|K|V projection (N=1536)
    {
        GemmP p { X216, PHID, w16 + 4 * PE * PE, PHID, nullptr, QKV16, 1536, bQKV, PHID, q_len };
        cudaLaunchConfig_t cfg = make_cfg(dim3(12, 32), dim3(256), 98304, &at);
        cudaLaunchKernelEx(&cfg, gemm_kernel, p);
    }

    // 9) fused self attention (masked keys) -> Op16
    {
        cudaLaunchConfig_t cfg = make_cfg(dim3(PLQ / 128, PH, PB), dim3(256), 81920, &at);
        cudaLaunchKernelEx(&cfg, flash2_kernel,
                           (const __half*)QKV16, 1536, (const __half*)(QKV16 + 512), 1536,
                           (const __half*)(QKV16 + 1024), 1536, Op16,
                           (float*)nullptr, (float*)nullptr, (int)PLQ, 1, q_len);
    }

    // 10) self out-projection
    {
        GemmP p { Op16, PHID, w16 + 7 * PE * PE, PHID, Pp, nullptr, PHID, sbo, PHID, q_len };
        cudaLaunchConfig_t cfg = make_cfg(dim3(4, 32), dim3(256), 98304, &at);
        cudaLaunchKernelEx(&cfg, gemm_kernel, p);
    }

    // 11) final LN, invalid rows zeroed
    {
        cudaLaunchConfig_t cfg = make_cfg(dim3(MQ), dim3(128), 0, &at);
        cudaLaunchKernelEx(&cfg, add_silu_ln_kernel,
                           (const float*)X2, (const float*)Pp, g_self, b_self,
                           out_q, (__half*)nullptr, q_len, 1);
    }
}

// round 16
// speedup vs baseline: 1.0658x; 1.0001x over previous
#include <cuda_runtime.h>
#include <cuda_fp16.h>
#include <cstdint>
#include <cstddef>

// Problem constants
#define PB   4
#define PLQ  1024
#define PLK  2048
#define PE   512
#define PHID 512
#define PH   8
#define PHD  64

// PDL: wait for predecessor's memory flush before touching global memory.
#define GDC_WAIT() asm volatile("griddepcontrol.wait;" ::: "memory")

// ---------------------------------------------------------------------------
// Scratch (__device__ globals; no runtime allocation allowed)
// ---------------------------------------------------------------------------
__device__ float  g_Pp[PB * PLQ * PE];
__device__ float  g_X1[PB * PLQ * PE];
__device__ float  g_Fb[PB * PLQ * PHID];
__device__ float  g_X2[PB * PLQ * PHID];

__device__ __half g_w16 [9 * PE * PE];     // cWq*, cWk, cWv, cWo, sWq*, sWk, sWv, sWo, Wf (* = prescaled 1/8)
__device__ __half g_keys16[PB * PLK * PE];
__device__ __half g_QM16 [PB * PLQ * PE];
__device__ __half g_Qp16 [PB * PLQ * PE];
__device__ __half g_KV16 [PB * PLK * 1024];
__device__ __half g_QKV16[PB * PLQ * 1536];
__device__ __half g_Op16 [PB * PLQ * PE];
__device__ __half g_X116 [PB * PLQ * PE];
__device__ __half g_X216 [PB * PLQ * PE];

__device__ float  g_bQ  [PE];
__device__ float  g_bKV [1024];
__device__ float  g_bQKV[1536];

__device__ float  g_sm[PB * PH * PLQ];
__device__ float  g_sl[PB * PH * PLQ];

// ---------------------------------------------------------------------------
// helpers
// ---------------------------------------------------------------------------
__device__ __forceinline__ void cpasync16(uint32_t dst, const void* src) {
    asm volatile("cp.async.cg.shared.global [%0], [%1], 16;" :: "r"(dst), "l"(src));
}
__device__ __forceinline__ void cpcommit() {
    asm volatile("cp.async.commit_group;");
}
__device__ __forceinline__ uint32_t packh2(float a, float b) {
    __half2 h = __floats2half2_rn(a, b);
    return *reinterpret_cast<uint32_t*>(&h);
}
__device__ __forceinline__ float ex2a(float x) {   // guaranteed single MUFU EX2
    float y;
    asm("ex2.approx.f32 %0, %1;" : "=f"(y) : "f"(x));
    return y;
}
#define L2E 1.44269504f

// ---------------------------------------------------------------------------
// GEMM body: C = A @ B^T + bias. CTA tile 128x128x64; 8 warps 2(M)x4(N).
// smem: sA 3*16KB @0, sB 3*16KB @49152 (dynamic >= 98304).
// ---------------------------------------------------------------------------
struct GemmP {
    const __half* A; int lda;
    const __half* B; int ldb;
    float* C32; __half* C16; int ldc;
    const float* bias;
    int K;
    const int* qlen;
};

__device__ void gemm_body(const GemmP p, int bx, int by)
{
    extern __shared__ char smem[];
    const uint32_t baseA = (uint32_t)__cvta_generic_to_shared(smem);
    const uint32_t baseB = baseA + 49152u;

    const int tid  = threadIdx.x;
    const int lane = tid & 31;
    const int warp = tid >> 5;
    const int wm   = warp >> 2;
    const int wn   = warp & 3;
    const int m0   = by * 128;
    const int n0   = bx * 128;

    if (p.qlen) {
        int b = m0 >> 10;
        int local = m0 & 1023;
        if (local >= p.qlen[b]) {
            for (int i = tid; i < 128 * 32; i += 256) {
                int r = i >> 5, c = (i & 31) * 4;
                if (p.C32) *reinterpret_cast<float4*>(p.C32 + (size_t)(m0 + r) * p.ldc + n0 + c) =
                    make_float4(0.f, 0.f, 0.f, 0.f);
                if (p.C16) *reinterpret_cast<uint2*>(p.C16 + (size_t)(m0 + r) * p.ldc + n0 + c) =
                    make_uint2(0u, 0u);
            }
            return;
        }
    }

    auto load_tile = [&](int stage, int k0) {
        #pragma unroll
        for (int i = 0; i < 4; i++) {
            int f = tid + i * 256;
            int r = f >> 3, c = f & 7;
            cpasync16(baseA + (uint32_t)stage * 16384u + (uint32_t)r * 128u + (uint32_t)((c ^ (r & 7)) << 4),
                      p.A + (size_t)(m0 + r) * p.lda + k0 + c * 8);
        }
        #pragma unroll
        for (int i = 0; i < 4; i++) {
            int f = tid + i * 256;
            int r = f >> 3, c = f & 7;
            cpasync16(baseB + (uint32_t)stage * 16384u + (uint32_t)r * 128u + (uint32_t)((c ^ (r & 7)) << 4),
                      p.B + (size_t)(n0 + r) * p.ldb + k0 + c * 8);
        }
        cpcommit();
    };

    float d[4][4][4];
    #pragma unroll
    for (int mi = 0; mi < 4; mi++)
        #pragma unroll
        for (int ni = 0; ni < 4; ni++)
            #pragma unroll
            for (int j = 0; j < 4; j++) d[mi][ni][j] = 0.f;

    const int nt = p.K >> 6;
    load_tile(0, 0);
    if (nt > 1) load_tile(1, 64);

    for (int t = 0; t < nt; t++) {
        if (t < nt - 1) { asm volatile("cp.async.wait_group 1;"); }
        else            { asm volatile("cp.async.wait_group 0;"); }
        __syncthreads();
        if (t + 2 < nt) load_tile((t + 2) % 3, (t + 2) << 6);

        const uint32_t stA = baseA + (uint32_t)(t % 3) * 16384u;
        const uint32_t stB = baseB + (uint32_t)(t % 3) * 16384u;

        #pragma unroll
        for (int ks = 0; ks < 4; ks++) {
            const int kb = ks * 16;
            uint32_t a[4][4], b[4][2];
            #pragma unroll
            for (int mi = 0; mi < 4; mi++) {
                int r  = wm * 64 + mi * 16 + (lane & 15);
                int ck = kb + ((lane >> 4) << 3);
                uint32_t addr = stA + (uint32_t)r * 128u + (uint32_t)((((ck >> 3) ^ (r & 7))) << 4);
                asm volatile("ldmatrix.sync.aligned.m8n8.x4.shared.b16 {%0,%1,%2,%3}, [%4];"
                             : "=r"(a[mi][0]), "=r"(a[mi][1]), "=r"(a[mi][2]), "=r"(a[mi][3])
                             : "r"(addr));
            }
            #pragma unroll
            for (int ni = 0; ni < 4; ni++) {
                int r  = wn * 32 + ni * 8 + (lane & 7);
                int ck = kb + (((lane >> 3) & 1) << 3);
                uint32_t addr = stB + (uint32_t)r * 128u + (uint32_t)((((ck >> 3) ^ (r & 7))) << 4);
                asm volatile("ldmatrix.sync.aligned.m8n8.x2.shared.b16 {%0,%1}, [%2];"
                             : "=r"(b[ni][0]), "=r"(b[ni][1])
                             : "r"(addr));
            }
            #pragma unroll
            for (int mi = 0; mi < 4; mi++)
                #pragma unroll
                for (int ni = 0; ni < 4; ni++) {
                    asm volatile(
                        "mma.sync.aligned.m16n8k16.row.col.f32.f16.f16.f32 "
                        "{%0,%1,%2,%3}, {%4,%5,%6,%7}, {%8,%9}, {%0,%1,%2,%3};"
                        : "+f"(d[mi][ni][0]), "+f"(d[mi][ni][1]),
                          "+f"(d[mi][ni][2]), "+f"(d[mi][ni][3])
                        : "r"(a[mi][0]), "r"(a[mi][1]), "r"(a[mi][2]), "r"(a[mi][3]),
                          "r"(b[ni][0]), "r"(b[ni][1]));
                }
        }
        __syncthreads();
    }

    const int g = lane >> 2, tq = lane & 3;
    #pragma unroll
    for (int mi = 0; mi < 4; mi++) {
        #pragma unroll
        for (int ni = 0; ni < 4; ni++) {
            int rr = m0 + wm * 64 + mi * 16 + g;
            int cc = n0 + wn * 32 + ni * 8 + tq * 2;
            float b0 = 0.f, b1 = 0.f;
            if (p.bias) { b0 = p.bias[cc]; b1 = p.bias[cc + 1]; }
            float o00 = d[mi][ni][0] + b0, o01 = d[mi][ni][1] + b1;
            float o10 = d[mi][ni][2] + b0, o11 = d[mi][ni][3] + b1;
            if (p.C32) {
                *reinterpret_cast<float2*>(p.C32 + (size_t)rr * p.ldc + cc)       = make_float2(o00, o01);
                *reinterpret_cast<float2*>(p.C32 + (size_t)(rr + 8) * p.ldc + cc) = make_float2(o10, o11);
            }
            if (p.C16) {
                *reinterpret_cast<__half2*>(p.C16 + (size_t)rr * p.ldc + cc)       = __floats2half2_rn(o00, o01);
                *reinterpret_cast<__half2*>(p.C16 + (size_t)(rr + 8) * p.ldc + cc) = __floats2half2_rn(o10, o11);
            }
        }
    }
}

// ---------------------------------------------------------------------------
// Weights body: one (qt -> 64-row q-tile, b, kz -> 512-key slice).
// Per 64-key stage loads FULL K rows (all 8 heads, 1KB/row), double-buffered;
// all 8 heads between two barriers. p = ex2(s*log2e + c), c = -m*log2e - log2(l).
// smem: sQ 0..64KB | sK 64KB..192KB (2 stg x 64KB) | sC @196608 (8x64 f32)
// total 198656.
// ---------------------------------------------------------------------------
__device__ void weights_body(int qt, int b, int kz,
                             const __half* __restrict__ Qp, const __half* __restrict__ Kp, int ldk,
                             const float* __restrict__ stats_m, const float* __restrict__ stats_l,
                             const int* __restrict__ q_len, float* __restrict__ wout)
{
    extern __shared__ char smem[];
    float* sC = reinterpret_cast<float*>(smem + 196608);

    const int q0 = qt * 64;
    const int tid = threadIdx.x, lane = tid & 31, warp = tid >> 5;
    const int wm = warp & 3, wn = warp >> 2;
    const int ql = q_len[b];

    if (q0 >= ql) {
        #pragma unroll
        for (int i = 0; i < 32; i++) {
            int f = tid + i * 256;
            int r = f >> 7, c = (f & 127) * 4;
            *reinterpret_cast<float4*>(wout + ((size_t)b * PLQ + q0 + r) * PLK + kz * 512 + c) =
                make_float4(0.f, 0.f, 0.f, 0.f);
        }
        return;
    }

    const uint32_t baseQ = (uint32_t)__cvta_generic_to_shared(smem);
    const uint32_t baseK = baseQ + 65536u;

    #pragma unroll
    for (int i = 0; i < 2; i++) {
        int j = tid + i * 256;
        int h = j >> 6, r = j & 63;
        size_t idx = ((size_t)b * PH + h) * PLQ + q0 + r;
        sC[j] = -stats_m[idx] * L2E - __log2f(stats_l[idx]);
    }

    const __half* Qb = Qp + ((size_t)b * PLQ + q0) * PE;
    #pragma unroll
    for (int i = 0; i < 16; i++) {
        int f = tid + i * 256;
        int r = f >> 6, c = f & 63;
        uint32_t off = (uint32_t)r * 1024u + (uint32_t)((((c & 7) ^ (r & 7)) | (c & 56)) << 4);
        cpasync16(baseQ + off, Qb + (size_t)r * PE + c * 8);
    }
    cpcommit();

    const __half* Kbase = Kp + ((size_t)b * PLK + kz * 512) * ldk;
    auto loadK = [&](int stage, int kt) {
        #pragma unroll
        for (int i = 0; i < 16; i++) {
            int f = tid + i * 256;
            int r = f >> 6, c = f & 63;
            uint32_t off = (uint32_t)r * 1024u + (uint32_t)((((c & 7) ^ (r & 7)) | (c & 56)) << 4);
            cpasync16(baseK + (uint32_t)stage * 65536u + off, Kbase + (size_t)(kt * 64 + r) * ldk + c * 8);
        }
        cpcommit();
    };
    loadK(0, 0);

    const int g = lane >> 2, tq = lane & 3;
    const int rr  = wm * 16 + g;
    const int rr8 = rr + 8;
    const bool v0 = (q0 + rr)  < ql;
    const bool v1 = (q0 + rr8) < ql;

    for (int it = 0; it < 8; it++) {
        if (it + 1 < 8) {
            loadK((it + 1) & 1, it + 1);
            asm volatile("cp.async.wait_group 1;");
        } else {
            asm volatile("cp.async.wait_group 0;");
        }
        __syncthreads();
        const uint32_t ko = (uint32_t)(it & 1) * 65536u;

        float acc[4][4];
        #pragma unroll
        for (int ni = 0; ni < 4; ni++)
            #pragma unroll
            for (int j = 0; j < 4; j++) acc[ni][j] = 0.f;

        for (int h = 0; h < 8; h++) {
            float d[4][4];
            #pragma unroll
            for (int ni = 0; ni < 4; ni++)
                #pragma unroll
                for (int j = 0; j < 4; j++) d[ni][j] = 0.f;

            #pragma unroll
            for (int ks = 0; ks < 4; ks++) {
                const int kb8 = ks * 2;
                uint32_t a[4];
                {
                    int r = wm * 16 + (lane & 15);
                    int c = h * 8 + kb8 + (lane >> 4);
                    uint32_t addr = baseQ + (uint32_t)r * 1024u + (uint32_t)((((c & 7) ^ (r & 7)) | (c & 56)) << 4);
                    asm volatile("ldmatrix.sync.aligned.m8n8.x4.shared.b16 {%0,%1,%2,%3}, [%4];"
                                 : "=r"(a[0]), "=r"(a[1]), "=r"(a[2]), "=r"(a[3]) : "r"(addr));
                }
                #pragma unroll
                for (int ni = 0; ni < 4; ni++) {
                    uint32_t b0, b1;
                    int r = wn * 32 + ni * 8 + (lane & 7);
                    int c = h * 8 + kb8 + ((lane >> 3) & 1);
                    uint32_t addr = baseK + ko + (uint32_t)r * 1024u + (uint32_t)((((c & 7) ^ (r & 7)) | (c & 56)) << 4);
                    asm volatile("ldmatrix.sync.aligned.m8n8.x2.shared.b16 {%0,%1}, [%2];"
                                 : "=r"(b0), "=r"(b1) : "r"(addr));
                    asm volatile(
                        "mma.sync.aligned.m16n8k16.row.col.f32.f16.f16.f32 "
                        "{%0,%1,%2,%3}, {%4,%5,%6,%7}, {%8,%9}, {%0,%1,%2,%3};"
                        : "+f"(d[ni][0]), "+f"(d[ni][1]), "+f"(d[ni][2]), "+f"(d[ni][3])
                        : "r"(a[0]), "r"(a[1]), "r"(a[2]), "r"(a[3]), "r"(b0), "r"(b1));
                }
            }

            float c0 = sC[h * 64 + rr];
            float c1 = sC[h * 64 + rr8];
            #pragma unroll
            for (int ni = 0; ni < 4; ni++) {
                acc[ni][0] += ex2a(fmaf(d[ni][0], L2E, c0));
                acc[ni][1] += ex2a(fmaf(d[ni][1], L2E, c0));
                acc[ni][2] += ex2a(fmaf(d[ni][2], L2E, c1));
                acc[ni][3] += ex2a(fmaf(d[ni][3], L2E, c1));
            }
        }

        int kbase = kz * 512 + it * 64;
        #pragma unroll
        for (int ni = 0; ni < 4; ni++) {
            int cc = kbase + wn * 32 + ni * 8 + tq * 2;
            float2 w0 = v0 ? make_float2(acc[ni][0] * 0.125f, acc[ni][1] * 0.125f)
                           : make_float2(0.f, 0.f);
            float2 w1 = v1 ? make_float2(acc[ni][2] * 0.125f, acc[ni][3] * 0.125f)
                           : make_float2(0.f, 0.f);
            *reinterpret_cast<float2*>(wout + ((size_t)b * PLQ + q0 + rr)  * PLK + cc) = w0;
            *reinterpret_cast<float2*>(wout + ((size_t)b * PLQ + q0 + rr8) * PLK + cc) = w1;
        }
        __syncthreads();
    }
}

// ---------------------------------------------------------------------------
// Kernel wrappers. gemm_kernel/dual_gemm_kernel request 2 CTAs/SM (<=128 regs)
// so the 98KB-smem GEMM actually co-resides twice per SM (reg file permitting).
// ---------------------------------------------------------------------------
__global__ __launch_bounds__(256, 2)
void gemm_kernel(GemmP p) { GDC_WAIT(); gemm_body(p, blockIdx.x, blockIdx.y); }

// z=0: GEMM p0 (full grid.xy). z=1: GEMM p1 in the top-left gx1 x gy1 corner.
__global__ __launch_bounds__(256, 2)
void dual_gemm_kernel(GemmP p0, GemmP p1, int gx1, int gy1)
{
    GDC_WAIT();
    if (blockIdx.z == 0) gemm_body(p0, blockIdx.x, blockIdx.y);
    else if ((int)blockIdx.x < gx1 && (int)blockIdx.y < gy1)
        gemm_body(p1, blockIdx.x, blockIdx.y);
}

// LPT ordering: z=0,1 -> long weights CTAs first; z=2 -> GEMM plane last.
// weights l in 0..255 -> kz(0..3), b, qt(0..15)
__global__ __launch_bounds__(256)
void gemm_weights_kernel(GemmP p,
                         const __half* Qp, const __half* Kp, int ldk,
                         const float* sm, const float* sl,
                         const int* q_len, float* wout)
{
    GDC_WAIT();
    if (blockIdx.z == 2) { gemm_body(p, blockIdx.x, blockIdx.y); return; }
    int l = blockIdx.z * (gridDim.x * gridDim.y) + blockIdx.y * gridDim.x + blockIdx.x;
    int kz  = l >> 6;
    int rem = l & 63;
    int b   = rem >> 4;
    int qt  = rem & 15;
    weights_body(qt, b, kz, Qp, Kp, ldk, sm, sl, q_len, wout);
}

// ---------------------------------------------------------------------------
// FA2 flash attention. 256 threads, q-tile 128 rows, KV tile 128 keys (2 halves).
// smem: sQ 0..16KB | sK 16K..48K (2 stg x 16KB) | sV 48K..80K (2 stg)
// ---------------------------------------------------------------------------
__global__ __launch_bounds__(256)
void flash2_kernel(const __half* __restrict__ Q, int ldq,
                   const __half* __restrict__ K, int ldk,
                   const __half* __restrict__ V, int ldv,
                   __half* __restrict__ O,
                   float* __restrict__ stats_m, float* __restrict__ stats_l,
                   int LK, int masked, const int* __restrict__ q_len)
{
    GDC_WAIT();
    extern __shared__ char smem[];
    const int b = blockIdx.z, h = blockIdx.y, q0 = blockIdx.x * 128;
    const int ql = q_len[b];
    if (q0 >= ql) return;

    const int tid = threadIdx.x, lane = tid & 31, warp = tid >> 5;
    const int limit = masked ? ql : LK;
    const int nt = (limit + 127) >> 7;

    const uint32_t baseQ = (uint32_t)__cvta_generic_to_shared(smem);
    const uint32_t baseK = baseQ + 16384u;
    const uint32_t baseV = baseQ + 49152u;

    const __half* Qb = Q + ((size_t)b * PLQ + q0) * ldq + h * PHD;
    const __half* Kb = K + ((size_t)b * LK) * ldk + h * PHD;
    const __half* Vb = V + ((size_t)b * LK) * ldv + h * PHD;

    #pragma unroll
    for (int i = 0; i < 4; i++) {
        int f = tid + i * 256;
        int r = f >> 3, c = f & 7;
        cpasync16(baseQ + (uint32_t)r * 128u + (uint32_t)((c ^ (r & 7)) << 4),
                  Qb + (size_t)r * ldq + c * 8);
    }
    auto loadKV = [&](int stage, int k0) {
        #pragma unroll
        for (int i = 0; i < 4; i++) {
            int f = tid + i * 256;
            int r = f >> 3, c = f & 7;
            cpasync16(baseK + stage * 16384u + (uint32_t)r * 128u + (uint32_t)((c ^ (r & 7)) << 4),
                      Kb + (size_t)(k0 + r) * ldk + c * 8);
        }
        #pragma unroll
        for (int i = 0; i < 4; i++) {
            int f = tid + i * 256;
            int r = f >> 3, c = f & 7;
            cpasync16(baseV + stage * 16384u + (uint32_t)r * 128u + (uint32_t)((c ^ (r & 7)) << 4),
                      Vb + (size_t)(k0 + r) * ldv + c * 8);
        }
        cpcommit();
    };
    loadKV(0, 0);

    float m0 = -3.0e38f, m1 = -3.0e38f, l0 = 0.f, l1 = 0.f;
    float o[8][4];
    #pragma unroll
    for (int ni = 0; ni < 8; ni++)
        #pragma unroll
        for (int j = 0; j < 4; j++) o[ni][j] = 0.f;

    for (int t = 0; t < nt; t++) {
        if (t + 1 < nt) {
            loadKV((t + 1) & 1, (t + 1) << 7);
            asm volatile("cp.async.wait_group 1;");
        } else {
            asm volatile("cp.async.wait_group 0;");
        }
        __syncthreads();
        const uint32_t kvo = (uint32_t)(t & 1) * 16384u;

        #pragma unroll
        for (int half = 0; half < 2; half++) {
            const int k0 = (t << 7) + (half << 6);
            if (k0 >= limit) break;
            const uint32_t kho = kvo + (uint32_t)half * 8192u;

            float d[8][4];
            #pragma unroll
            for (int ni = 0; ni < 8; ni++)
                #pragma unroll
                for (int j = 0; j < 4; j++) d[ni][j] = 0.f;

            #pragma unroll
            for (int ks = 0; ks < 4; ks++) {
                const int kb = ks * 16;
                uint32_t a[4];
                {
                    int r  = warp * 16 + (lane & 15);
                    int ck = kb + ((lane >> 4) << 3);
                    uint32_t addr = baseQ + (uint32_t)r * 128u + (uint32_t)((((ck >> 3) ^ (r & 7))) << 4);
                    asm volatile("ldmatrix.sync.aligned.m8n8.x4.shared.b16 {%0,%1,%2,%3}, [%4];"
                                 : "=r"(a[0]), "=r"(a[1]), "=r"(a[2]), "=r"(a[3]) : "r"(addr));
                }
                #pragma unroll
                for (int ni = 0; ni < 8; ni++) {
                    uint32_t b0, b1;
                    int r  = ni * 8 + (lane & 7);
                    int ck = kb + (((lane >> 3) & 1) << 3);
                    uint32_t addr = baseK + kho + (uint32_t)r * 128u + (uint32_t)((((ck >> 3) ^ (r & 7))) << 4);
                    asm volatile("ldmatrix.sync.aligned.m8n8.x2.shared.b16 {%0,%1}, [%2];"
                                 : "=r"(b0), "=r"(b1) : "r"(addr));
                    asm volatile(
                        "mma.sync.aligned.m16n8k16.row.col.f32.f16.f16.f32 "
                        "{%0,%1,%2,%3}, {%4,%5,%6,%7}, {%8,%9}, {%0,%1,%2,%3};"
                        : "+f"(d[ni][0]), "+f"(d[ni][1]), "+f"(d[ni][2]), "+f"(d[ni][3])
                        : "r"(a[0]), "r"(a[1]), "r"(a[2]), "r"(a[3]), "r"(b0), "r"(b1));
                }
            }

            const bool doMask = masked && (k0 + 64 > limit);
            float t0 = -3.0e38f, t1 = -3.0e38f;
            #pragma unroll
            for (int ni = 0; ni < 8; ni++) {
                if (doMask) {
                    int c0 = k0 + ni * 8 + (lane & 3) * 2;
                    if (c0 >= limit)     { d[ni][0] = -3.0e38f; d[ni][2] = -3.0e38f; }
                    if (c0 + 1 >= limit) { d[ni][1] = -3.0e38f; d[ni][3] = -3.0e38f; }
                }
                t0 = fmaxf(t0, fmaxf(d[ni][0], d[ni][1]));
                t1 = fmaxf(t1, fmaxf(d[ni][2], d[ni][3]));
            }
            t0 = fmaxf(t0, __shfl_xor_sync(0xffffffffu, t0, 1));
            t0 = fmaxf(t0, __shfl_xor_sync(0xffffffffu, t0, 2));
            t1 = fmaxf(t1, __shfl_xor_sync(0xffffffffu, t1, 1));
            t1 = fmaxf(t1, __shfl_xor_sync(0xffffffffu, t1, 2));
            float mn0 = fmaxf(m0, t0), mn1 = fmaxf(m1, t1);
            float fr0 = __expf(m0 - mn0), fr1 = __expf(m1 - mn1);
            m0 = mn0; m1 = mn1;

            float s0 = 0.f, s1 = 0.f;
            uint32_t pf[8][2];
            #pragma unroll
            for (int ni = 0; ni < 8; ni++) {
                float e0 = __expf(d[ni][0] - mn0), e1 = __expf(d[ni][1] - mn0);
                float e2 = __expf(d[ni][2] - mn1), e3 = __expf(d[ni][3] - mn1);
                s0 += e0 + e1; s1 += e2 + e3;
                pf[ni][0] = packh2(e0, e1);
                pf[ni][1] = packh2(e2, e3);
            }
            s0 += __shfl_xor_sync(0xffffffffu, s0, 1);
            s0 += __shfl_xor_sync(0xffffffffu, s0, 2);
            s1 += __shfl_xor_sync(0xffffffffu, s1, 1);
            s1 += __shfl_xor_sync(0xffffffffu, s1, 2);
            l0 = l0 * fr0 + s0;
            l1 = l1 * fr1 + s1;
            #pragma unroll
            for (int ni = 0; ni < 8; ni++) {
                o[ni][0] *= fr0; o[ni][1] *= fr0;
                o[ni][2] *= fr1; o[ni][3] *= fr1;
            }

            #pragma unroll
            for (int j = 0; j < 4; j++) {
                uint32_t a0 = pf[2 * j][0], a1 = pf[2 * j][1];
                uint32_t a2 = pf[2 * j + 1][0], a3 = pf[2 * j + 1][1];
                #pragma unroll
                for (int ni = 0; ni < 8; ni++) {
                    uint32_t b0, b1;
                    int r = j * 16 + (lane & 15);
                    uint32_t addr = baseV + kho + (uint32_t)r * 128u + (uint32_t)(((ni ^ (r & 7))) << 4);
                    asm volatile("ldmatrix.sync.aligned.m8n8.x2.trans.shared.b16 {%0,%1}, [%2];"
                                 : "=r"(b0), "=r"(b1) : "r"(addr));
                    asm volatile(
                        "mma.sync.aligned.m16n8k16.row.col.f32.f16.f16.f32 "
                        "{%0,%1,%2,%3}, {%4,%5,%6,%7}, {%8,%9}, {%0,%1,%2,%3};"
                        : "+f"(o[ni][0]), "+f"(o[ni][1]), "+f"(o[ni][2]), "+f"(o[ni][3])
                        : "r"(a0), "r"(a1), "r"(a2), "r"(a3), "r"(b0), "r"(b1));
                }
            }
        }
        __syncthreads();
    }

    const int g = lane >> 2, tq = lane & 3;
    const int r0 = warp * 16 + g;
    float il0 = 1.0f / l0, il1 = 1.0f / l1;
    __half* Ob = O + ((size_t)b * PLQ + q0) * PE + h * PHD;
    #pragma unroll
    for (int ni = 0; ni < 8; ni++) {
        int cc = ni * 8 + tq * 2;
        *reinterpret_cast<__half2*>(Ob + (size_t)r0 * PE + cc) =
            __floats2half2_rn(o[ni][0] * il0, o[ni][1] * il0);
        *reinterpret_cast<__half2*>(Ob + (size_t)(r0 + 8) * PE + cc) =
            __floats2half2_rn(o[ni][2] * il1, o[ni][3] * il1);
    }
    if (stats_m && tq == 0) {
        size_t idx = ((size_t)b * PH + h) * PLQ + q0 + r0;
        stats_m[idx] = m0;  stats_l[idx] = l0;
        stats_m[idx + 8] = m1;  stats_l[idx + 8] = l1;
    }
}

// ---------------------------------------------------------------------------
// prep kernel: weight convert (+Wq prescale), keys f32->f16, bias pack,
// query mask (fp16 only). grid.x = 2304 + 4096 + 2 + 2048 = 8450, 256 threads
// ---------------------------------------------------------------------------
struct Ptr9 { const float* p[9]; };
__global__ __launch_bounds__(256)
void prep_kernel(Ptr9 ps, __half* __restrict__ w16,
                 const float* __restrict__ keys, __half* __restrict__ keys16,
                 const float* cbq, const float* cbk, const float* cbv,
                 const float* sbq, const float* sbk, const float* sbv,
                 float* bQ, float* bKV, float* bQKV,
                 const float* __restrict__ queries,
                 __half* __restrict__ QM16, const int* __restrict__ q_len)
{
    GDC_WAIT();
    int bid = blockIdx.x;
    int tid = threadIdx.x;
    if (bid < 2304) {
        int m = bid >> 8;
        float sc = (m == 0 || m == 4) ? 0.125f : 1.0f;
        int i = ((bid & 255) * 256 + tid) * 4;
        float4 v = *reinterpret_cast<const float4*>(ps.p[m] + i);
        __half2* o = reinterpret_cast<__half2*>(w16 + (size_t)m * PE * PE + i);
        o[0] = __floats2half2_rn(v.x * sc, v.y * sc);
        o[1] = __floats2half2_rn(v.z * sc, v.w * sc);
    } else if (bid < 2304 + 4096) {
        int i = ((bid - 2304) * 256 + tid) * 4;
        float4 v = *reinterpret_cast<const float4*>(keys + i);
        __half2* o = reinterpret_cast<__half2*>(keys16 + i);
        o[0] = __floats2half2_rn(v.x, v.y);
        o[1] = __floats2half2_rn(v.z, v.w);
    } else if (bid < 2304 + 4096 + 2) {
        int i = (bid - 6400) * 256 + tid;     // 0..511
        bQ[i]          = cbq[i] * 0.125f;
        bKV[i]         = cbk[i];
        bKV[512 + i]   = cbv[i];
        bQKV[i]        = sbq[i] * 0.125f;
        bQKV[512 + i]  = sbk[i];
        bQKV[1024 + i] = sbv[i];
    } else {
        int r = (bid - 6402) * 2 + (tid >> 7);
        int c = (tid & 127);
        bool valid = (r % PLQ) < q_len[r / PLQ];
        float4 v = valid ? reinterpret_cast<const float4*>(queries + (size_t)r * PE)[c]
                         : make_float4(0.f, 0.f, 0.f, 0.f);
        __half2* dh = reinterpret_cast<__half2*>(QM16 + (size_t)r * PE) + c * 2;
        dh[0] = __floats2half2_rn(v.x, v.y);
        dh[1] = __floats2half2_rn(v.z, v.w);
    }
}

// ---------------------------------------------------------------------------
// out[r,:] = LN( silu(X + Y) )*g + b ; optional fp16 copy; optional zero rows
// ---------------------------------------------------------------------------
__global__ __launch_bounds__(128)
void add_silu_ln_kernel(const float* __restrict__ X, const float* __restrict__ Y,
                        const float* __restrict__ g, const float* __restrict__ bln,
                        float* __restrict__ out, __half* __restrict__ out16,
                        const int* __restrict__ q_len, int zero_invalid)
{
    GDC_WAIT();
    constexpr int D = 512;
    int r = blockIdx.x;
    int tid = threadIdx.x;
    int c = tid * 4;

    float4 x = *reinterpret_cast<const float4*>(X + (size_t)r * D + c);
    float4 y = *reinterpret_cast<const float4*>(Y + (size_t)r * D + c);
    float v[4] = {x.x + y.x, x.y + y.y, x.z + y.z, x.w + y.w};

    float s[4], sum = 0.f, sumsq = 0.f;
    #pragma unroll
    for (int i = 0; i < 4; i++) {
        s[i] = v[i] / (1.0f + __expf(-v[i]));
        sum += s[i];
        sumsq += s[i] * s[i];
    }

    __shared__ float r1[128], r2[128];
    r1[tid] = sum; r2[tid] = sumsq; __syncthreads();
    for (int st = 64; st > 0; st >>= 1) {
        if (tid < st) { r1[tid] += r1[tid + st]; r2[tid] += r2[tid + st]; }
        __syncthreads();
    }
    float mu  = r1[0] * (1.0f / D);
    float var = r2[0] * (1.0f / D) - mu * mu;
    float rs  = rsqrtf(var + 1e-5f);

    bool zero = zero_invalid && ((r % PLQ) >= q_len[r / PLQ]);

    float4 gg = *reinterpret_cast<const float4*>(g + c);
    float4 bb = *reinterpret_cast<const float4*>(bln + c);
    float4 o;
    o.x = zero ? 0.f : (s[0] - mu) * rs * gg.x + bb.x;
    o.y = zero ? 0.f : (s[1] - mu) * rs * gg.y + bb.y;
    o.z = zero ? 0.f : (s[2] - mu) * rs * gg.z + bb.z;
    o.w = zero ? 0.f : (s[3] - mu) * rs * gg.w + bb.w;
    *reinterpret_cast<float4*>(out + (size_t)r * D + c) = o;
    if (out16) {
        __half2* oh = reinterpret_cast<__half2*>(out16 + (size_t)r * D + c);
        oh[0] = __floats2half2_rn(o.x, o.y);
        oh[1] = __floats2half2_rn(o.z, o.w);
    }
}

// ---------------------------------------------------------------------------
// Host launcher (all launches PDL-serialized: dependents pre-launch and wait)
// ---------------------------------------------------------------------------
static cudaLaunchConfig_t make_cfg(dim3 grid, dim3 block, size_t smem,
                                   cudaLaunchAttribute* attr)
{
    attr->id = cudaLaunchAttributeProgrammaticStreamSerialization;
    attr->val.programmaticStreamSerializationAllowed = 1;
    cudaLaunchConfig_t cfg{};
    cfg.gridDim = grid;
    cfg.blockDim = block;
    cfg.dynamicSmemBytes = smem;
    cfg.stream = 0;
    cfg.attrs = attr;
    cfg.numAttrs = 1;
    return cfg;
}

extern "C" void kernel_launch(void* const* d_in, const int* in_sizes, int n_in,
                              void* d_out, int out_size)
{
    const float* queries = (const float*)d_in[0];
    const float* keys    = (const float*)d_in[1];
    const int*   q_len   = (const int*)  d_in[2];
    const float* cWq = (const float*)d_in[3];  const float* cbq = (const float*)d_in[4];
    const float* cWk = (const float*)d_in[5];  const float* cbk = (const float*)d_in[6];
    const float* cWv = (const float*)d_in[7];  const float* cbv = (const float*)d_in[8];
    const float* cWo = (const float*)d_in[9];  const float* cbo = (const float*)d_in[10];
    const float* sWq = (const float*)d_in[11]; const float* sbq = (const float*)d_in[12];
    const float* sWk = (const float*)d_in[13]; const float* sbk = (const float*)d_in[14];
    const float* sWv = (const float*)d_in[15]; const float* sbv = (const float*)d_in[16];
    const float* sWo = (const float*)d_in[17]; const float* sbo = (const float*)d_in[18];
    const float* Wf  = (const float*)d_in[19]; const float* bf  = (const float*)d_in[20];
    const float* g_cross = (const float*)d_in[21]; const float* b_cross = (const float*)d_in[22];
    const float* g_ffn   = (const float*)d_in[23]; const float* b_ffn   = (const float*)d_in[24];
    const float* g_self  = (const float*)d_in[25]; const float* b_self  = (const float*)d_in[26];

    float* out_q = (float*)d_out;
    float* out_w = out_q + (size_t)PB * PLQ * PHID;

    float *Pp, *X1, *Fb, *X2, *sm, *sl, *bQ, *bKV, *bQKV;
    __half *w16, *keys16, *QM16, *Qp16, *KV16, *QKV16, *Op16, *X116, *X216;
    cudaGetSymbolAddress((void**)&Pp,   g_Pp);
    cudaGetSymbolAddress((void**)&X1,   g_X1);
    cudaGetSymbolAddress((void**)&Fb,   g_Fb);
    cudaGetSymbolAddress((void**)&X2,   g_X2);
    cudaGetSymbolAddress((void**)&sm,   g_sm);
    cudaGetSymbolAddress((void**)&sl,   g_sl);
    cudaGetSymbolAddress((void**)&bQ,   g_bQ);
    cudaGetSymbolAddress((void**)&bKV,  g_bKV);
    cudaGetSymbolAddress((void**)&bQKV, g_bQKV);
    cudaGetSymbolAddress((void**)&w16,  g_w16);
    cudaGetSymbolAddress((void**)&keys16, g_keys16);
    cudaGetSymbolAddress((void**)&QM16, g_QM16);
    cudaGetSymbolAddress((void**)&Qp16, g_Qp16);
    cudaGetSymbolAddress((void**)&KV16, g_KV16);
    cudaGetSymbolAddress((void**)&QKV16, g_QKV16);
    cudaGetSymbolAddress((void**)&Op16, g_Op16);
    cudaGetSymbolAddress((void**)&X116, g_X116);
    cudaGetSymbolAddress((void**)&X216, g_X216);

    cudaFuncSetAttribute(gemm_kernel,          cudaFuncAttributeMaxDynamicSharedMemorySize, 98304);
    cudaFuncSetAttribute(dual_gemm_kernel,     cudaFuncAttributeMaxDynamicSharedMemorySize, 98304);
    cudaFuncSetAttribute(gemm_weights_kernel,  cudaFuncAttributeMaxDynamicSharedMemorySize, 198656);
    cudaFuncSetAttribute(flash2_kernel,        cudaFuncAttributeMaxDynamicSharedMemorySize, 81920);

    const int MQ = PB * PLQ;   // 4096
    cudaLaunchAttribute at;

    // 1) prep: weight/keys convert, bias pack, query masking (fp16 only)
    Ptr9 ps;
    ps.p[0] = cWq; ps.p[1] = cWk; ps.p[2] = cWv; ps.p[3] = cWo;
    ps.p[4] = sWq; ps.p[5] = sWk; ps.p[6] = sWv; ps.p[7] = sWo; ps.p[8] = Wf;
    {
        cudaLaunchConfig_t cfg = make_cfg(dim3(8450), dim3(256), 0, &at);
        cudaLaunchKernelEx(&cfg, prep_kernel, ps, w16, keys, keys16,
                           cbq, cbk, cbv, sbq, sbk, sbv, bQ, bKV, bQKV,
                           queries, QM16, q_len);
    }

    // 2) cross projections: merged K|V GEMM (z=0) + Q GEMM (z=1)
    {
        GemmP pKV { keys16, PE, w16 + 1 * PE * PE, PE, nullptr, KV16, 1024, bKV, PE, nullptr };
        GemmP pQ  { QM16,   PE, w16 + 0 * PE * PE, PE, nullptr, Qp16, PE,   bQ,  PE, q_len };
        cudaLaunchConfig_t cfg = make_cfg(dim3(8, 64, 2), dim3(256), 98304, &at);
        cudaLaunchKernelEx(&cfg, dual_gemm_kernel, pKV, pQ, 4, 32);
    }

    // 3) fused cross attention -> Op16 (+ stats)
    {
        cudaLaunchConfig_t cfg = make_cfg(dim3(PLQ / 128, PH, PB), dim3(256), 81920, &at);
        cudaLaunchKernelEx(&cfg, flash2_kernel,
                           (const __half*)Qp16, (int)PE, (const __half*)KV16, 1024,
                           (const __half*)(KV16 + 512), 1024, Op16, sm, sl,
                           (int)PLK, 0, q_len);
    }

    // 4) ALL weights slices (z=0,1, long CTAs first) + cross out-projection (z=2)
    {
        GemmP p { Op16, PE, w16 + 3 * PE * PE, PE, Pp, nullptr, PE, cbo, PE, q_len };
        cudaLaunchConfig_t cfg = make_cfg(dim3(4, 32, 3), dim3(256), 198656, &at);
        cudaLaunchKernelEx(&cfg, gemm_weights_kernel, p,
                           (const __half*)Qp16, (const __half*)KV16, 1024,
                           (const float*)sm, (const float*)sl, q_len, out_w);
    }

    // 5) x1 = LN(silu(cross + queries))   (invalid rows garbage-but-finite, dead downstream)
    {
        cudaLaunchConfig_t cfg = make_cfg(dim3(MQ), dim3(128), 0, &at);
        cudaLaunchKernelEx(&cfg, add_silu_ln_kernel,
                           (const float*)Pp, queries, g_cross, b_cross,
                           X1, X116, q_len, 0);
    }

    // 6) FFN GEMM
    {
        GemmP p { X116, PE, w16 + 8 * PE * PE, PE, Fb, nullptr, PHID, bf, PE, q_len };
        cudaLaunchConfig_t cfg = make_cfg(dim3(4, 32), dim3(256), 98304, &at);
        cudaLaunchKernelEx(&cfg, gemm_kernel, p);
    }

    // 7) x2 = LN(silu(x1 + ffn))
    {
        cudaLaunchConfig_t cfg = make_cfg(dim3(MQ), dim3(128), 0, &at);
        cudaLaunchKernelEx(&cfg, add_silu_ln_kernel,
                           (const float*)X1, (const float*)Fb, g_ffn, b_ffn,
                           X2, X216, q_len, 0);
    }

    // 8) merged self Q|K|V projection (N=1536)
    {
        GemmP p { X216, PHID, w16 + 4 * PE * PE, PHID, nullptr, QKV16, 1536, bQKV, PHID, q_len };
        cudaLaunchConfig_t cfg = make_cfg(dim3(12, 32), dim3(256), 98304, &at);
        cudaLaunchKernelEx(&cfg, gemm_kernel, p);
    }

    // 9) fused self attention (masked keys) -> Op16
    {
        cudaLaunchConfig_t cfg = make_cfg(dim3(PLQ / 128, PH, PB), dim3(256), 81920, &at);
        cudaLaunchKernelEx(&cfg, flash2_kernel,
                           (const __half*)QKV16, 1536, (const __half*)(QKV16 + 512), 1536,
                           (const __half*)(QKV16 + 1024), 1536, Op16,
                           (float*)nullptr, (float*)nullptr, (int)PLQ, 1, q_len);
    }

    // 10) self out-projection
    {
        GemmP p { Op16, PHID, w16 + 7 * PE * PE, PHID, Pp, nullptr, PHID, sbo, PHID, q_len };
        cudaLaunchConfig_t cfg = make_cfg(dim3(4, 32), dim3(256), 98304, &at);
        cudaLaunchKernelEx(&cfg, gemm_kernel, p);
    }

    // 11) final LN, invalid rows zeroed
    {
        cudaLaunchConfig_t cfg = make_cfg(dim3(MQ), dim3(128), 0, &at);
        cudaLaunchKernelEx(&cfg, add_silu_ln_kernel,
                           (const float*)X2, (const float*)Pp, g_self, b_self,
                           out_q, (__half*)nullptr, q_len, 1);
    }
}